// round 12
// baseline (speedup 1.0000x reference)
#include <cuda_runtime.h>
#include <math.h>

// Problem constants
#define Bc 2
#define Tc 512
#define Cc 1024
#define Ec 8
#define KTOP 2
#define NHc 8
#define HSc 128
#define AHc 1024
#define NTOK 1024      // B*T
#define NBATCH 32      // B*KTOP*NH

// ---------------- scratch (static device globals; NEVER passed from host) ----
__device__ __align__(256) float d_q  [(size_t)NTOK*KTOP*AHc];  // rows (t*2+slot)
__device__ __align__(256) float d_k  [(size_t)NTOK*AHc];
__device__ __align__(256) float d_v  [(size_t)NTOK*AHc];
__device__ __align__(256) float d_att[(size_t)NBATCH*Tc*Tc];   // [bb][i][j]
__device__ __align__(256) float d_yw [(size_t)NTOK*KTOP*AHc];  // gate-scaled y
__device__ float d_gates[NTOK*KTOP];
__device__ float d_probs[NTOK*Ec];
__device__ int   d_cnt [Ec];
__device__ int   d_list[Ec][NTOK];   // encoded (token<<1)|slot

// ---------------- zero init (out accumulates atomics; cnt reset) ----------------
__global__ void zero_kernel(float* __restrict__ out) {
    int i = blockIdx.x * blockDim.x + threadIdx.x;
    if (i < NTOK * Cc) out[i] = 0.f;
    if (i < Ec) d_cnt[i] = 0;
}

// ---------------- gating: warp per token ----------------
__global__ void gate_kernel(const float* __restrict__ x, const float* __restrict__ Wg) {
    int warp = (blockIdx.x * blockDim.x + threadIdx.x) >> 5;
    int lane = threadIdx.x & 31;
    if (warp >= NTOK) return;
    const float* xr = x + (size_t)warp * Cc;
    float acc[Ec];
#pragma unroll
    for (int e = 0; e < Ec; e++) acc[e] = 0.f;
    for (int c = lane; c < Cc; c += 32) {
        float xv = xr[c];
        const float* w = Wg + (size_t)c * Ec;
#pragma unroll
        for (int e = 0; e < Ec; e++) acc[e] += xv * w[e];
    }
#pragma unroll
    for (int off = 16; off; off >>= 1)
#pragma unroll
        for (int e = 0; e < Ec; e++) acc[e] += __shfl_down_sync(0xffffffffu, acc[e], off);

    if (lane == 0) {
        float v1 = -1e30f, v2 = -1e30f; int i1 = 0, i2 = 0;
#pragma unroll
        for (int e = 0; e < Ec; e++) {
            float a = acc[e];
            if (a > v1)      { v2 = v1; i2 = i1; v1 = a; i1 = e; }
            else if (a > v2) { v2 = a; i2 = e; }
        }
        float g1 = 1.f / (1.f + expf(v2 - v1));
        d_gates[warp * 2 + 0] = g1;
        d_gates[warp * 2 + 1] = 1.f - g1;
        float s = 0.f, ex[Ec];
#pragma unroll
        for (int e = 0; e < Ec; e++) { ex[e] = expf(acc[e] - v1); s += ex[e]; }
        float inv = 1.f / s;
#pragma unroll
        for (int e = 0; e < Ec; e++) d_probs[warp * Ec + e] = ex[e] * inv;
        int p0 = atomicAdd(&d_cnt[i1], 1); d_list[i1][p0] = (warp << 1) | 0;
        int p1 = atomicAdd(&d_cnt[i2], 1); d_list[i2][p1] = (warp << 1) | 1;
    }
}

// ---------------- aux loss (deterministic tree reduce) ----------------
__global__ void aux_kernel(float* __restrict__ out, int out_size) {
    __shared__ float sh[256];
    int tid = threadIdx.x;
    float aux = 0.f;
    for (int e = 0; e < Ec; e++) {
        float s = 0.f;
        for (int t = tid; t < NTOK; t += 256) s += d_probs[t * Ec + e];
        sh[tid] = s; __syncthreads();
        for (int off = 128; off; off >>= 1) {
            if (tid < off) sh[tid] += sh[tid + off];
            __syncthreads();
        }
        if (tid == 0) aux += (sh[0] / (float)NTOK) * ((float)d_cnt[e] / (float)NTOK);
        __syncthreads();
    }
    if (tid == 0 && out_size > NTOK * Cc) out[out_size - 1] = (float)Ec * aux;
}

// ---------------- generic 64x64x16 fp32 GEMM ----------------
// MODE 0: dense x@Wk + bk -> d_k       MODE 1: dense x@Wv + bv -> d_v
// MODE 2: grouped q: rows of x gathered via d_list[e], @W_in[e] -> d_q[enc]
// MODE 3: grouped out: rows d_yw[enc] @ W_out[e] -> atomicAdd out[(enc>>1)*N+n]
template<int MODE>
__global__ __launch_bounds__(256) void sgemm64(
    const float* __restrict__ A, const float* __restrict__ Bmat,
    const float* __restrict__ bias, float* __restrict__ Cext,
    int N, int Kdim)
{
    const int e = blockIdx.z;
    const int cnt = (MODE <= 1) ? NTOK : d_cnt[e];
    const int m0 = blockIdx.y * 64;
    if (m0 >= cnt) return;
    const int n0 = blockIdx.x * 64;
    const float* Bp = (MODE <= 1) ? Bmat : (Bmat + (size_t)e * Kdim * N);
    const float* Ab = (MODE == 3) ? d_yw : A;   // device-side scratch selection

    __shared__ float As[16][65];
    __shared__ float Bs[16][64];

    const int tid = threadIdx.x;
    const int a_m = tid >> 2;
    const int a_k = (tid & 3) << 2;
    const int b_k = tid >> 4;
    const int b_n = (tid & 15) << 2;
    const int ty = tid >> 4;
    const int tx = tid & 15;

    int row_enc = 0; bool loadv = true;
    if (MODE <= 1) row_enc = m0 + a_m;
    else {
        int r = m0 + a_m;
        if (r < cnt) row_enc = d_list[e][r]; else loadv = false;
    }
    const float* Arow = Ab;
    if (loadv) {
        int ar_idx = (MODE == 2) ? (row_enc >> 1) : row_enc;
        Arow = Ab + (size_t)ar_idx * Kdim;
    }

    float acc[4][4] = {};

    for (int k0 = 0; k0 < Kdim; k0 += 16) {
        float4 a4 = loadv ? *(const float4*)(Arow + k0 + a_k) : make_float4(0.f,0.f,0.f,0.f);
        As[a_k + 0][a_m] = a4.x; As[a_k + 1][a_m] = a4.y;
        As[a_k + 2][a_m] = a4.z; As[a_k + 3][a_m] = a4.w;
        *(float4*)(&Bs[b_k][b_n]) = *(const float4*)(Bp + (size_t)(k0 + b_k) * N + n0 + b_n);
        __syncthreads();
#pragma unroll
        for (int k = 0; k < 16; k++) {
            float a0 = As[k][ty*4+0], a1 = As[k][ty*4+1];
            float a2 = As[k][ty*4+2], a3 = As[k][ty*4+3];
            float4 b4 = *(const float4*)(&Bs[k][tx*4]);
            acc[0][0] += a0*b4.x; acc[0][1] += a0*b4.y; acc[0][2] += a0*b4.z; acc[0][3] += a0*b4.w;
            acc[1][0] += a1*b4.x; acc[1][1] += a1*b4.y; acc[1][2] += a1*b4.z; acc[1][3] += a1*b4.w;
            acc[2][0] += a2*b4.x; acc[2][1] += a2*b4.y; acc[2][2] += a2*b4.z; acc[2][3] += a2*b4.w;
            acc[3][0] += a3*b4.x; acc[3][1] += a3*b4.y; acc[3][2] += a3*b4.z; acc[3][3] += a3*b4.w;
        }
        __syncthreads();
    }

#pragma unroll
    for (int i = 0; i < 4; i++) {
        int r = m0 + ty * 4 + i;
        if (MODE >= 2 && r >= cnt) continue;
        int enc2 = (MODE <= 1) ? r : d_list[e][r];
        float* crow;
        if (MODE == 0)      crow = d_k  + (size_t)r * N;
        else if (MODE == 1) crow = d_v  + (size_t)r * N;
        else if (MODE == 2) crow = d_q  + (size_t)enc2 * N;
        else                crow = Cext + (size_t)(enc2 >> 1) * N;
#pragma unroll
        for (int j = 0; j < 4; j++) {
            int n = n0 + tx * 4 + j;
            float val = acc[i][j];
            if (MODE <= 1)      crow[n] = val + bias[n];
            else if (MODE == 2) crow[n] = val;
            else atomicAdd(&crow[n], val);
        }
    }
}

// ---------------- attention logits: S = Q K^T / sqrt(HS), causal tiles only ---
__global__ __launch_bounds__(256) void attn_qk() {
    const int jt = blockIdx.x, it = blockIdx.y, bb = blockIdx.z;
    if (jt > it) return;
    const int b = bb >> 4, kk = (bb >> 3) & 1, h = bb & 7;

    __shared__ float Qs[16][65];
    __shared__ float Ks[16][65];

    const int tid = threadIdx.x;
    const int a_m = tid >> 2;
    const int a_k = (tid & 3) << 2;
    const int ty = tid >> 4, tx = tid & 15;

    const float* qrow = d_q + ((size_t)(b * Tc + it * 64 + a_m) * 2 + kk) * AHc + h * HSc;
    const float* krow = d_k + (size_t)(b * Tc + jt * 64 + a_m) * AHc + h * HSc;

    float acc[4][4] = {};
    for (int k0 = 0; k0 < HSc; k0 += 16) {
        float4 q4 = *(const float4*)(qrow + k0 + a_k);
        Qs[a_k+0][a_m] = q4.x; Qs[a_k+1][a_m] = q4.y; Qs[a_k+2][a_m] = q4.z; Qs[a_k+3][a_m] = q4.w;
        float4 k4 = *(const float4*)(krow + k0 + a_k);
        Ks[a_k+0][a_m] = k4.x; Ks[a_k+1][a_m] = k4.y; Ks[a_k+2][a_m] = k4.z; Ks[a_k+3][a_m] = k4.w;
        __syncthreads();
#pragma unroll
        for (int k = 0; k < 16; k++) {
            float a0 = Qs[k][ty*4+0], a1 = Qs[k][ty*4+1];
            float a2 = Qs[k][ty*4+2], a3 = Qs[k][ty*4+3];
            float b0 = Ks[k][tx*4+0], b1 = Ks[k][tx*4+1];
            float b2 = Ks[k][tx*4+2], b3 = Ks[k][tx*4+3];
            acc[0][0]+=a0*b0; acc[0][1]+=a0*b1; acc[0][2]+=a0*b2; acc[0][3]+=a0*b3;
            acc[1][0]+=a1*b0; acc[1][1]+=a1*b1; acc[1][2]+=a1*b2; acc[1][3]+=a1*b3;
            acc[2][0]+=a2*b0; acc[2][1]+=a2*b1; acc[2][2]+=a2*b2; acc[2][3]+=a2*b3;
            acc[3][0]+=a3*b0; acc[3][1]+=a3*b1; acc[3][2]+=a3*b2; acc[3][3]+=a3*b3;
        }
        __syncthreads();
    }
    const float scale = 0.08838834764831845f; // 1/sqrt(128)
    float* orow = d_att + (size_t)bb * (Tc * Tc) + (size_t)(it * 64) * Tc + jt * 64;
#pragma unroll
    for (int i = 0; i < 4; i++)
#pragma unroll
        for (int j = 0; j < 4; j++)
            orow[(size_t)(ty*4+i) * Tc + tx*4 + j] = acc[i][j] * scale;
}

// ---------------- stick-breaking transform, in place (parallel scan) ----------
// w[i,k] = exp(lz_k + sum_{j=k+1..i} lb_j); writes 0 above diagonal.
__device__ __forceinline__ float logsig(float a) {
    return (a >= 0.f) ? -__logf(1.f + __expf(-a)) : (a - __logf(1.f + __expf(a)));
}

__global__ __launch_bounds__(256) void stickbreak() {
    const int row = blockIdx.x;          // 0..NBATCH*Tc-1
    const int bb = row >> 9;
    const int i = row & (Tc - 1);
    float* ap = d_att + (size_t)bb * (Tc * Tc) + (size_t)i * Tc;
    const int tid = threadIdx.x;
    const int j0 = tid * 2, j1 = tid * 2 + 1;
    const bool v0 = (j0 <= i), v1 = (j1 <= i);

    float lz0 = 0.f, lb0 = 0.f, lz1 = 0.f, lb1 = 0.f;
    if (v0) { float a = ap[j0]; lz0 = logsig(a); lb0 = lz0 - a; }
    if (v1) { float a = ap[j1]; lz1 = logsig(a); lb1 = lz1 - a; }

    __shared__ float sc[256];
    float s = lb0 + lb1;
    sc[tid] = s; __syncthreads();
#pragma unroll
    for (int off = 1; off < 256; off <<= 1) {
        float t = (tid >= off) ? sc[tid - off] : 0.f;
        __syncthreads();
        sc[tid] += t;
        __syncthreads();
    }
    const float total = sc[255];
    const float excl = sc[tid] - s;
    float w0 = v0 ? __expf(lz0 + (total - (excl + lb0))) : 0.f;
    float w1 = v1 ? __expf(lz1 + (total - (excl + lb0 + lb1))) : 0.f;
    ap[j0] = w0; ap[j1] = w1;
}

// ---------------- y = att @ V, gate-scaled, causal k-tile skipping -----------
__global__ __launch_bounds__(256) void attn_av() {
    const int nt = blockIdx.x, it = blockIdx.y, bb = blockIdx.z;
    const int b = bb >> 4, kk = (bb >> 3) & 1, h = bb & 7;
    const int n0 = nt * 64;
    const int kmax = (it + 1) * 64;

    __shared__ float As[16][65];
    __shared__ float Bs[16][64];

    const int tid = threadIdx.x;
    const int a_m = tid >> 2;
    const int a_k = (tid & 3) << 2;
    const int b_k = tid >> 4;
    const int b_n = (tid & 15) << 2;
    const int ty = tid >> 4, tx = tid & 15;

    const float* abase = d_att + (size_t)bb * (Tc * Tc) + (size_t)(it * 64 + a_m) * Tc;
    const float* vbase = d_v + (size_t)(b * Tc) * AHc + h * HSc;

    float acc[4][4] = {};
    for (int k0 = 0; k0 < kmax; k0 += 16) {
        float4 a4 = *(const float4*)(abase + k0 + a_k);
        As[a_k+0][a_m] = a4.x; As[a_k+1][a_m] = a4.y; As[a_k+2][a_m] = a4.z; As[a_k+3][a_m] = a4.w;
        *(float4*)(&Bs[b_k][b_n]) = *(const float4*)(vbase + (size_t)(k0 + b_k) * AHc + n0 + b_n);
        __syncthreads();
#pragma unroll
        for (int k = 0; k < 16; k++) {
            float a0 = As[k][ty*4+0], a1 = As[k][ty*4+1];
            float a2 = As[k][ty*4+2], a3 = As[k][ty*4+3];
            float4 b4 = *(const float4*)(&Bs[k][tx*4]);
            acc[0][0]+=a0*b4.x; acc[0][1]+=a0*b4.y; acc[0][2]+=a0*b4.z; acc[0][3]+=a0*b4.w;
            acc[1][0]+=a1*b4.x; acc[1][1]+=a1*b4.y; acc[1][2]+=a1*b4.z; acc[1][3]+=a1*b4.w;
            acc[2][0]+=a2*b4.x; acc[2][1]+=a2*b4.y; acc[2][2]+=a2*b4.z; acc[2][3]+=a2*b4.w;
            acc[3][0]+=a3*b4.x; acc[3][1]+=a3*b4.y; acc[3][2]+=a3*b4.z; acc[3][3]+=a3*b4.w;
        }
        __syncthreads();
    }
#pragma unroll
    for (int i = 0; i < 4; i++) {
        int token = b * Tc + it * 64 + ty * 4 + i;
        float g = d_gates[token * 2 + kk];
        float* yrow = d_yw + ((size_t)token * 2 + kk) * AHc + h * HSc + n0;
#pragma unroll
        for (int j = 0; j < 4; j++)
            yrow[tx * 4 + j] = acc[i][j] * g;
    }
}

// ---------------- launch ----------------
extern "C" void kernel_launch(void* const* d_in, const int* in_sizes, int n_in,
                              void* d_out, int out_size) {
    const float* x     = (const float*)d_in[0];
    const float* Wg    = (const float*)d_in[1];
    const float* W_in  = (const float*)d_in[2];
    const float* W_out = (const float*)d_in[3];
    const float* Wk    = (const float*)d_in[4];
    const float* bk    = (const float*)d_in[5];
    const float* Wv    = (const float*)d_in[6];
    const float* bv    = (const float*)d_in[7];
    float* out = (float*)d_out;

    zero_kernel<<<(NTOK * Cc + 255) / 256, 256>>>(out);
    gate_kernel<<<(NTOK * 32 + 127) / 128, 128>>>(x, Wg);

    // K, V projections (dense 1024x1024x1024)
    sgemm64<0><<<dim3(16, 16, 1), 256>>>(x, Wk, bk, nullptr, AHc, Cc);
    sgemm64<1><<<dim3(16, 16, 1), 256>>>(x, Wv, bv, nullptr, AHc, Cc);

    // grouped q projection (per expert, gathered rows of x)
    sgemm64<2><<<dim3(16, 16, Ec), 256>>>(x, W_in, nullptr, nullptr, AHc, Cc);

    // attention logits (causal tiles)
    attn_qk<<<dim3(8, 8, NBATCH), 256>>>();

    // stick-breaking weights in place
    stickbreak<<<NBATCH * Tc, 256>>>();

    // y = att @ V, gate scaled
    attn_av<<<dim3(2, 8, NBATCH), 256>>>();

    // grouped output projection, scatter-add into out
    sgemm64<3><<<dim3(16, 16, Ec), 256>>>(nullptr, W_out, nullptr, out, Cc, AHc);

    // aux loss scalar
    aux_kernel<<<1, 256>>>(out, out_size);
}

// round 13
// speedup vs baseline: 1.0721x; 1.0721x over previous
#include <cuda_runtime.h>
#include <math.h>

// Problem constants
#define Bc 2
#define Tc 512
#define Cc 1024
#define Ec 8
#define KTOP 2
#define NHc 8
#define HSc 128
#define AHc 1024
#define NTOK 1024      // B*T
#define NBATCH 32      // B*KTOP*NH

// ---------------- scratch (static device globals; NEVER passed from host) ----
__device__ __align__(256) float d_q  [(size_t)NTOK*KTOP*AHc];  // rows (t*2+slot)
__device__ __align__(256) float d_k  [(size_t)NTOK*AHc];
__device__ __align__(256) float d_v  [(size_t)NTOK*AHc];
__device__ __align__(256) float d_att[(size_t)NBATCH*Tc*Tc];   // [bb][i][j]
__device__ __align__(256) float d_yw [(size_t)NTOK*KTOP*AHc];  // gate-scaled y
__device__ float d_gates[NTOK*KTOP];
__device__ float d_probs[NTOK*Ec];
__device__ int   d_cnt [Ec];
__device__ int   d_list[Ec][NTOK];   // encoded (token<<1)|slot

// ---------------- zero init ----------------
__global__ void zero_kernel(float* __restrict__ out) {
    int i = blockIdx.x * blockDim.x + threadIdx.x;
    if (i < NTOK * Cc) out[i] = 0.f;
    if (i < Ec) d_cnt[i] = 0;
}

// ---------------- gating: warp per token ----------------
__global__ void gate_kernel(const float* __restrict__ x, const float* __restrict__ Wg) {
    int warp = (blockIdx.x * blockDim.x + threadIdx.x) >> 5;
    int lane = threadIdx.x & 31;
    if (warp >= NTOK) return;
    const float* xr = x + (size_t)warp * Cc;
    float acc[Ec];
#pragma unroll
    for (int e = 0; e < Ec; e++) acc[e] = 0.f;
    for (int c = lane; c < Cc; c += 32) {
        float xv = xr[c];
        const float* w = Wg + (size_t)c * Ec;
#pragma unroll
        for (int e = 0; e < Ec; e++) acc[e] += xv * w[e];
    }
#pragma unroll
    for (int off = 16; off; off >>= 1)
#pragma unroll
        for (int e = 0; e < Ec; e++) acc[e] += __shfl_down_sync(0xffffffffu, acc[e], off);

    if (lane == 0) {
        float v1 = -1e30f, v2 = -1e30f; int i1 = 0, i2 = 0;
#pragma unroll
        for (int e = 0; e < Ec; e++) {
            float a = acc[e];
            if (a > v1)      { v2 = v1; i2 = i1; v1 = a; i1 = e; }
            else if (a > v2) { v2 = a; i2 = e; }
        }
        float g1 = 1.f / (1.f + expf(v2 - v1));
        d_gates[warp * 2 + 0] = g1;
        d_gates[warp * 2 + 1] = 1.f - g1;
        float s = 0.f, ex[Ec];
#pragma unroll
        for (int e = 0; e < Ec; e++) { ex[e] = expf(acc[e] - v1); s += ex[e]; }
        float inv = 1.f / s;
#pragma unroll
        for (int e = 0; e < Ec; e++) d_probs[warp * Ec + e] = ex[e] * inv;
        int p0 = atomicAdd(&d_cnt[i1], 1); d_list[i1][p0] = (warp << 1) | 0;
        int p1 = atomicAdd(&d_cnt[i2], 1); d_list[i2][p1] = (warp << 1) | 1;
    }
}

// ---------------- aux loss ----------------
__global__ void aux_kernel(float* __restrict__ out, int out_size) {
    __shared__ float sh[256];
    int tid = threadIdx.x;
    float aux = 0.f;
    for (int e = 0; e < Ec; e++) {
        float s = 0.f;
        for (int t = tid; t < NTOK; t += 256) s += d_probs[t * Ec + e];
        sh[tid] = s; __syncthreads();
        for (int off = 128; off; off >>= 1) {
            if (tid < off) sh[tid] += sh[tid + off];
            __syncthreads();
        }
        if (tid == 0) aux += (sh[0] / (float)NTOK) * ((float)d_cnt[e] / (float)NTOK);
        __syncthreads();
    }
    if (tid == 0 && out_size > NTOK * Cc) out[out_size - 1] = (float)Ec * aux;
}

// ================= 128x64x16 fp32 GEMM, 256 thr, 8x4 microtile ===============
// MODE 0: x@Wk+bk -> d_k   MODE 1: x@Wv+bv -> d_v
// MODE 2: grouped q (gather x rows via d_list) -> d_q
// MODE 3: grouped out (d_yw rows) -> atomicAdd Cext
template<int MODE>
__global__ __launch_bounds__(256) void gemm128(
    const float* __restrict__ A, const float* __restrict__ Bmat,
    const float* __restrict__ bias, float* __restrict__ Cext,
    int N, int Kdim)
{
    const int e = blockIdx.z;
    const int cnt = (MODE <= 1) ? NTOK : d_cnt[e];
    const int m0 = blockIdx.y * 128;
    if (m0 >= cnt) return;
    const int n0 = blockIdx.x * 64;
    const float* Bp = (MODE <= 1) ? Bmat : (Bmat + (size_t)e * Kdim * N);

    __shared__ float As[16][132];   // [k][m], padded
    __shared__ float Bs[16][68];    // [k][n], padded (16B-aligned rows)

    const int tid = threadIdx.x;
    const int a_m = tid >> 1;              // 0..127
    const int a_k = (tid & 1) << 3;        // 0 or 8
    const int b_k = tid >> 4;              // 0..15
    const int b_n = (tid & 15) << 2;       // 0..60
    const int ty = tid >> 4;               // 0..15 -> rows ty*8..+7
    const int tx = tid & 15;               // 0..15 -> cols tx*4..+3

    int enc = 0; bool loadv = true;
    if (MODE <= 1) enc = m0 + a_m;
    else {
        int r = m0 + a_m;
        if (r < cnt) enc = d_list[e][r]; else loadv = false;
    }
    const float* Arow;
    if (MODE <= 1)      Arow = A + (size_t)enc * Kdim;
    else if (MODE == 2) Arow = A + (size_t)(enc >> 1) * Kdim;
    else                Arow = d_yw + (size_t)enc * Kdim;

    float acc[8][4] = {};

    for (int k0 = 0; k0 < Kdim; k0 += 16) {
        float4 A0 = make_float4(0.f,0.f,0.f,0.f), A1 = A0;
        if (loadv) {
            A0 = *(const float4*)(Arow + k0 + a_k);
            A1 = *(const float4*)(Arow + k0 + a_k + 4);
        }
        As[a_k + 0][a_m] = A0.x; As[a_k + 1][a_m] = A0.y;
        As[a_k + 2][a_m] = A0.z; As[a_k + 3][a_m] = A0.w;
        As[a_k + 4][a_m] = A1.x; As[a_k + 5][a_m] = A1.y;
        As[a_k + 6][a_m] = A1.z; As[a_k + 7][a_m] = A1.w;
        *(float4*)(&Bs[b_k][b_n]) = *(const float4*)(Bp + (size_t)(k0 + b_k) * N + n0 + b_n);
        __syncthreads();
#pragma unroll
        for (int k = 0; k < 16; k++) {
            float4 aL = *(const float4*)(&As[k][ty * 8]);
            float4 aH = *(const float4*)(&As[k][ty * 8 + 4]);
            float4 bV = *(const float4*)(&Bs[k][tx * 4]);
            float av[8] = {aL.x, aL.y, aL.z, aL.w, aH.x, aH.y, aH.z, aH.w};
#pragma unroll
            for (int i = 0; i < 8; i++) {
                acc[i][0] = fmaf(av[i], bV.x, acc[i][0]);
                acc[i][1] = fmaf(av[i], bV.y, acc[i][1]);
                acc[i][2] = fmaf(av[i], bV.z, acc[i][2]);
                acc[i][3] = fmaf(av[i], bV.w, acc[i][3]);
            }
        }
        __syncthreads();
    }

    float4 bias4 = make_float4(0.f,0.f,0.f,0.f);
    if (MODE <= 1) bias4 = *(const float4*)(bias + n0 + tx * 4);

#pragma unroll
    for (int i = 0; i < 8; i++) {
        int r = m0 + ty * 8 + i;
        if (MODE >= 2 && r >= cnt) continue;
        int enc2 = (MODE <= 1) ? r : d_list[e][r];
        if (MODE <= 1) {
            float* crow = (MODE == 0 ? d_k : d_v) + (size_t)r * N + n0 + tx * 4;
            float4 v = make_float4(acc[i][0] + bias4.x, acc[i][1] + bias4.y,
                                   acc[i][2] + bias4.z, acc[i][3] + bias4.w);
            *(float4*)crow = v;
        } else if (MODE == 2) {
            float* crow = d_q + (size_t)enc2 * N + n0 + tx * 4;
            *(float4*)crow = make_float4(acc[i][0], acc[i][1], acc[i][2], acc[i][3]);
        } else {
            float* crow = Cext + (size_t)(enc2 >> 1) * N + n0 + tx * 4;
            atomicAdd(&crow[0], acc[i][0]);
            atomicAdd(&crow[1], acc[i][1]);
            atomicAdd(&crow[2], acc[i][2]);
            atomicAdd(&crow[3], acc[i][3]);
        }
    }
}

// ============ attention logits: S = Q K^T / sqrt(HS), 128x64 causal tiles ====
__global__ __launch_bounds__(256) void attn_qk() {
    const int jt = blockIdx.x, it = blockIdx.y, bb = blockIdx.z;
    if (jt > 2 * it + 1) return;           // tile fully above diagonal
    const int b = bb >> 4, kk = (bb >> 3) & 1, h = bb & 7;

    __shared__ float As[16][132];          // [d][i]
    __shared__ float Bs[16][68];           // [d][j]

    const int tid = threadIdx.x;
    const int a_m = tid >> 1;
    const int a_k = (tid & 1) << 3;
    const int n_r = tid >> 2;              // 0..63 (k-row for B load)
    const int d_o = (tid & 3) << 2;        // 0,4,8,12
    const int ty = tid >> 4, tx = tid & 15;

    const float* qrow = d_q + ((size_t)(b * Tc + it * 128 + a_m) * 2 + kk) * AHc + h * HSc;
    const float* krow = d_k + (size_t)(b * Tc + jt * 64 + n_r) * AHc + h * HSc;

    float acc[8][4] = {};

    for (int k0 = 0; k0 < HSc; k0 += 16) {
        float4 A0 = *(const float4*)(qrow + k0 + a_k);
        float4 A1 = *(const float4*)(qrow + k0 + a_k + 4);
        As[a_k + 0][a_m] = A0.x; As[a_k + 1][a_m] = A0.y;
        As[a_k + 2][a_m] = A0.z; As[a_k + 3][a_m] = A0.w;
        As[a_k + 4][a_m] = A1.x; As[a_k + 5][a_m] = A1.y;
        As[a_k + 6][a_m] = A1.z; As[a_k + 7][a_m] = A1.w;
        float4 Kv = *(const float4*)(krow + k0 + d_o);
        Bs[d_o + 0][n_r] = Kv.x; Bs[d_o + 1][n_r] = Kv.y;
        Bs[d_o + 2][n_r] = Kv.z; Bs[d_o + 3][n_r] = Kv.w;
        __syncthreads();
#pragma unroll
        for (int k = 0; k < 16; k++) {
            float4 aL = *(const float4*)(&As[k][ty * 8]);
            float4 aH = *(const float4*)(&As[k][ty * 8 + 4]);
            float4 bV = *(const float4*)(&Bs[k][tx * 4]);
            float av[8] = {aL.x, aL.y, aL.z, aL.w, aH.x, aH.y, aH.z, aH.w};
#pragma unroll
            for (int i = 0; i < 8; i++) {
                acc[i][0] = fmaf(av[i], bV.x, acc[i][0]);
                acc[i][1] = fmaf(av[i], bV.y, acc[i][1]);
                acc[i][2] = fmaf(av[i], bV.z, acc[i][2]);
                acc[i][3] = fmaf(av[i], bV.w, acc[i][3]);
            }
        }
        __syncthreads();
    }
    const float scale = 0.08838834764831845f; // 1/sqrt(128)
    float* obase = d_att + (size_t)bb * (Tc * Tc) + (size_t)(it * 128) * Tc + jt * 64;
#pragma unroll
    for (int i = 0; i < 8; i++) {
        float* crow = obase + (size_t)(ty * 8 + i) * Tc + tx * 4;
        *(float4*)crow = make_float4(acc[i][0] * scale, acc[i][1] * scale,
                                     acc[i][2] * scale, acc[i][3] * scale);
    }
}

// ---------------- stick-breaking transform, in place (parallel scan) ----------
__device__ __forceinline__ float logsig(float a) {
    return (a >= 0.f) ? -__logf(1.f + __expf(-a)) : (a - __logf(1.f + __expf(a)));
}

__global__ __launch_bounds__(256) void stickbreak() {
    const int row = blockIdx.x;
    const int bb = row >> 9;
    const int i = row & (Tc - 1);
    float* ap = d_att + (size_t)bb * (Tc * Tc) + (size_t)i * Tc;
    const int tid = threadIdx.x;
    const int j0 = tid * 2, j1 = tid * 2 + 1;
    const bool v0 = (j0 <= i), v1 = (j1 <= i);

    float lz0 = 0.f, lb0 = 0.f, lz1 = 0.f, lb1 = 0.f;
    if (v0) { float a = ap[j0]; lz0 = logsig(a); lb0 = lz0 - a; }
    if (v1) { float a = ap[j1]; lz1 = logsig(a); lb1 = lz1 - a; }

    __shared__ float sc[256];
    float s = lb0 + lb1;
    sc[tid] = s; __syncthreads();
#pragma unroll
    for (int off = 1; off < 256; off <<= 1) {
        float t = (tid >= off) ? sc[tid - off] : 0.f;
        __syncthreads();
        sc[tid] += t;
        __syncthreads();
    }
    const float total = sc[255];
    const float excl = sc[tid] - s;
    float w0 = v0 ? __expf(lz0 + (total - (excl + lb0))) : 0.f;
    float w1 = v1 ? __expf(lz1 + (total - (excl + lb0 + lb1))) : 0.f;
    ap[j0] = w0; ap[j1] = w1;
}

// ============ y = att @ V, gate-scaled, 128x64 tiles, causal k skip ==========
__global__ __launch_bounds__(256) void attn_av() {
    const int nt = blockIdx.x, it = blockIdx.y, bb = blockIdx.z;
    const int b = bb >> 4, kk = (bb >> 3) & 1, h = bb & 7;
    const int n0 = nt * 64;
    const int kmax = (it + 1) * 128;

    __shared__ float As[16][132];
    __shared__ float Bs[16][68];

    const int tid = threadIdx.x;
    const int a_m = tid >> 1;
    const int a_k = (tid & 1) << 3;
    const int b_k = tid >> 4;
    const int b_n = (tid & 15) << 2;
    const int ty = tid >> 4, tx = tid & 15;

    const float* arow = d_att + (size_t)bb * (Tc * Tc) + (size_t)(it * 128 + a_m) * Tc;
    const float* vbase = d_v + (size_t)(b * Tc) * AHc + h * HSc;

    float acc[8][4] = {};

    for (int k0 = 0; k0 < kmax; k0 += 16) {
        float4 A0 = *(const float4*)(arow + k0 + a_k);
        float4 A1 = *(const float4*)(arow + k0 + a_k + 4);
        As[a_k + 0][a_m] = A0.x; As[a_k + 1][a_m] = A0.y;
        As[a_k + 2][a_m] = A0.z; As[a_k + 3][a_m] = A0.w;
        As[a_k + 4][a_m] = A1.x; As[a_k + 5][a_m] = A1.y;
        As[a_k + 6][a_m] = A1.z; As[a_k + 7][a_m] = A1.w;
        *(float4*)(&Bs[b_k][b_n]) = *(const float4*)(vbase + (size_t)(k0 + b_k) * AHc + n0 + b_n);
        __syncthreads();
#pragma unroll
        for (int k = 0; k < 16; k++) {
            float4 aL = *(const float4*)(&As[k][ty * 8]);
            float4 aH = *(const float4*)(&As[k][ty * 8 + 4]);
            float4 bV = *(const float4*)(&Bs[k][tx * 4]);
            float av[8] = {aL.x, aL.y, aL.z, aL.w, aH.x, aH.y, aH.z, aH.w};
#pragma unroll
            for (int i = 0; i < 8; i++) {
                acc[i][0] = fmaf(av[i], bV.x, acc[i][0]);
                acc[i][1] = fmaf(av[i], bV.y, acc[i][1]);
                acc[i][2] = fmaf(av[i], bV.z, acc[i][2]);
                acc[i][3] = fmaf(av[i], bV.w, acc[i][3]);
            }
        }
        __syncthreads();
    }
#pragma unroll
    for (int i = 0; i < 8; i++) {
        int token = b * Tc + it * 128 + ty * 8 + i;
        float g = d_gates[token * 2 + kk];
        float* yrow = d_yw + ((size_t)token * 2 + kk) * AHc + h * HSc + n0 + tx * 4;
        *(float4*)yrow = make_float4(acc[i][0] * g, acc[i][1] * g,
                                     acc[i][2] * g, acc[i][3] * g);
    }
}

// ---------------- launch ----------------
extern "C" void kernel_launch(void* const* d_in, const int* in_sizes, int n_in,
                              void* d_out, int out_size) {
    const float* x     = (const float*)d_in[0];
    const float* Wg    = (const float*)d_in[1];
    const float* W_in  = (const float*)d_in[2];
    const float* W_out = (const float*)d_in[3];
    const float* Wk    = (const float*)d_in[4];
    const float* bk    = (const float*)d_in[5];
    const float* Wv    = (const float*)d_in[6];
    const float* bv    = (const float*)d_in[7];
    float* out = (float*)d_out;

    zero_kernel<<<(NTOK * Cc + 255) / 256, 256>>>(out);
    gate_kernel<<<(NTOK * 32 + 127) / 128, 128>>>(x, Wg);

    // K, V projections (dense 1024x1024x1024)
    gemm128<0><<<dim3(16, 8, 1), 256>>>(x, Wk, bk, nullptr, AHc, Cc);
    gemm128<1><<<dim3(16, 8, 1), 256>>>(x, Wv, bv, nullptr, AHc, Cc);

    // grouped q projection (per expert, gathered rows of x)
    gemm128<2><<<dim3(16, 8, Ec), 256>>>(x, W_in, nullptr, nullptr, AHc, Cc);

    // attention logits (causal 128x64 tiles)
    attn_qk<<<dim3(8, 4, NBATCH), 256>>>();

    // stick-breaking weights in place
    stickbreak<<<NBATCH * Tc, 256>>>();

    // y = att @ V, gate scaled
    attn_av<<<dim3(2, 4, NBATCH), 256>>>();

    // grouped output projection, scatter-add into out
    gemm128<3><<<dim3(16, 8, Ec), 256>>>(nullptr, W_out, nullptr, out, Cc, AHc);

    // aux loss scalar
    aux_kernel<<<1, 256>>>(out, out_size);
}

// round 14
// speedup vs baseline: 1.1981x; 1.1176x over previous
#include <cuda_runtime.h>
#include <math.h>

// Problem constants
#define Bc 2
#define Tc 512
#define Cc 1024
#define Ec 8
#define KTOP 2
#define NHc 8
#define HSc 128
#define AHc 1024
#define NTOK 1024      // B*T
#define NBATCH 32      // B*KTOP*NH

// ---------------- scratch (static device globals; NEVER passed from host) ----
__device__ __align__(256) float d_q  [(size_t)NTOK*KTOP*AHc];  // rows (t*2+slot)
__device__ __align__(256) float d_k  [(size_t)NTOK*AHc];
__device__ __align__(256) float d_v  [(size_t)NTOK*AHc];
__device__ __align__(256) float d_att[(size_t)NBATCH*Tc*Tc];   // [bb][i][j]
__device__ __align__(256) float d_yw [(size_t)NTOK*KTOP*AHc];  // gate-scaled y
__device__ float d_gates[NTOK*KTOP];
__device__ float d_probs[NTOK*Ec];
__device__ int   d_cnt [Ec];
__device__ int   d_list[Ec][NTOK];   // encoded (token<<1)|slot

// ---------------- packed f32x2 helpers ----------------
typedef unsigned long long u64t;
__device__ __forceinline__ u64t pk2(float lo, float hi) {
    u64t r; asm("mov.b64 %0, {%1, %2};" : "=l"(r) : "f"(lo), "f"(hi)); return r;
}
__device__ __forceinline__ u64t splat2(float v) {
    u64t r; asm("mov.b64 %0, {%1, %1};" : "=l"(r) : "f"(v)); return r;
}
__device__ __forceinline__ void upk2(u64t v, float& lo, float& hi) {
    asm("mov.b64 {%0, %1}, %2;" : "=f"(lo), "=f"(hi) : "l"(v));
}
__device__ __forceinline__ void fma2(u64t& d, u64t a, u64t b) {
    asm("fma.rn.f32x2 %0, %1, %2, %3;" : "=l"(d) : "l"(a), "l"(b), "l"(d));
}

// microkernel: 16 k-steps over one smem stage; acc rows pair-packed.
// ty in 0..7 (rows ty*8..+7), tx in 0..15 (cols tx*4..+3)
__device__ __forceinline__ void mk16(const float (*__restrict__ As)[72],
                                     const float (*__restrict__ Bs)[72],
                                     u64t (&acc)[4][4], int ty, int tx)
{
#pragma unroll
    for (int k = 0; k < 16; k++) {
        float4 aL = *(const float4*)&As[k][ty * 8];
        float4 aH = *(const float4*)&As[k][ty * 8 + 4];
        float4 bV = *(const float4*)&Bs[k][tx * 4];
        u64t a0 = pk2(aL.x, aL.y), a1 = pk2(aL.z, aL.w);
        u64t a2 = pk2(aH.x, aH.y), a3 = pk2(aH.z, aH.w);
        u64t b0 = splat2(bV.x), b1 = splat2(bV.y), b2 = splat2(bV.z), b3 = splat2(bV.w);
        fma2(acc[0][0], a0, b0); fma2(acc[0][1], a0, b1); fma2(acc[0][2], a0, b2); fma2(acc[0][3], a0, b3);
        fma2(acc[1][0], a1, b0); fma2(acc[1][1], a1, b1); fma2(acc[1][2], a1, b2); fma2(acc[1][3], a1, b3);
        fma2(acc[2][0], a2, b0); fma2(acc[2][1], a2, b1); fma2(acc[2][2], a2, b2); fma2(acc[2][3], a2, b3);
        fma2(acc[3][0], a3, b0); fma2(acc[3][1], a3, b1); fma2(acc[3][2], a3, b2); fma2(acc[3][3], a3, b3);
    }
}

__device__ __forceinline__ void unpack_acc(u64t (&acc)[4][4], float (&vals)[8][4]) {
#pragma unroll
    for (int p = 0; p < 4; p++)
#pragma unroll
        for (int j = 0; j < 4; j++)
            upk2(acc[p][j], vals[2 * p][j], vals[2 * p + 1][j]);
}

// ---------------- zero init ----------------
__global__ void zero_kernel(float* __restrict__ out) {
    int i = blockIdx.x * blockDim.x + threadIdx.x;
    if (i < NTOK * Cc) out[i] = 0.f;
    if (i < Ec) d_cnt[i] = 0;
}

// ---------------- gating: warp per token ----------------
__global__ void gate_kernel(const float* __restrict__ x, const float* __restrict__ Wg) {
    int warp = (blockIdx.x * blockDim.x + threadIdx.x) >> 5;
    int lane = threadIdx.x & 31;
    if (warp >= NTOK) return;
    const float* xr = x + (size_t)warp * Cc;
    float acc[Ec];
#pragma unroll
    for (int e = 0; e < Ec; e++) acc[e] = 0.f;
    for (int c = lane; c < Cc; c += 32) {
        float xv = xr[c];
        const float* w = Wg + (size_t)c * Ec;
#pragma unroll
        for (int e = 0; e < Ec; e++) acc[e] += xv * w[e];
    }
#pragma unroll
    for (int off = 16; off; off >>= 1)
#pragma unroll
        for (int e = 0; e < Ec; e++) acc[e] += __shfl_down_sync(0xffffffffu, acc[e], off);

    if (lane == 0) {
        float v1 = -1e30f, v2 = -1e30f; int i1 = 0, i2 = 0;
#pragma unroll
        for (int e = 0; e < Ec; e++) {
            float a = acc[e];
            if (a > v1)      { v2 = v1; i2 = i1; v1 = a; i1 = e; }
            else if (a > v2) { v2 = a; i2 = e; }
        }
        float g1 = 1.f / (1.f + expf(v2 - v1));
        d_gates[warp * 2 + 0] = g1;
        d_gates[warp * 2 + 1] = 1.f - g1;
        float s = 0.f, ex[Ec];
#pragma unroll
        for (int e = 0; e < Ec; e++) { ex[e] = expf(acc[e] - v1); s += ex[e]; }
        float inv = 1.f / s;
#pragma unroll
        for (int e = 0; e < Ec; e++) d_probs[warp * Ec + e] = ex[e] * inv;
        int p0 = atomicAdd(&d_cnt[i1], 1); d_list[i1][p0] = (warp << 1) | 0;
        int p1 = atomicAdd(&d_cnt[i2], 1); d_list[i2][p1] = (warp << 1) | 1;
    }
}

// ---------------- aux loss ----------------
__global__ void aux_kernel(float* __restrict__ out, int out_size) {
    __shared__ float sh[256];
    int tid = threadIdx.x;
    float aux = 0.f;
    for (int e = 0; e < Ec; e++) {
        float s = 0.f;
        for (int t = tid; t < NTOK; t += 256) s += d_probs[t * Ec + e];
        sh[tid] = s; __syncthreads();
        for (int off = 128; off; off >>= 1) {
            if (tid < off) sh[tid] += sh[tid + off];
            __syncthreads();
        }
        if (tid == 0) aux += (sh[0] / (float)NTOK) * ((float)d_cnt[e] / (float)NTOK);
        __syncthreads();
    }
    if (tid == 0 && out_size > NTOK * Cc) out[out_size - 1] = (float)Ec * aux;
}

// ======== 64x64x16 double-buffered GEMM, 128 threads, f32x2 FMA ========
// MODE 0: dense. z=0: x@Wk+bk->d_k ; z=1: x@Wv+bv->d_v
// MODE 1: grouped q (gather x rows via d_list[z]) -> d_q
// MODE 2: grouped out (d_yw rows via d_list[z]) -> atomicAdd Cext
template<int MODE>
__global__ __launch_bounds__(128) void gemm_db(
    const float* __restrict__ x,
    const float* __restrict__ W0, const float* __restrict__ b0,
    const float* __restrict__ W1, const float* __restrict__ b1,
    float* __restrict__ Cext, int N, int Kdim)
{
    const int z = blockIdx.z;
    const int cnt = (MODE == 0) ? NTOK : d_cnt[z];
    const int m0 = blockIdx.y * 64;
    if (m0 >= cnt) return;
    const int n0 = blockIdx.x * 64;
    const float* Bp;
    const float* bias = nullptr;
    if (MODE == 0) { Bp = z ? W1 : W0; bias = z ? b1 : b0; }
    else            Bp = W0 + (size_t)z * Kdim * N;

    __shared__ float As[2][16][72];
    __shared__ float Bs[2][16][72];

    const int tid = threadIdx.x;
    const int a_m = tid >> 1;            // 0..63
    const int a_k = (tid & 1) << 3;      // 0/8
    const int b_k = tid >> 3;            // 0..15
    const int b_n = (tid & 7) << 3;      // 0..56
    const int ty  = tid >> 4;            // 0..7
    const int tx  = tid & 15;            // 0..15

    bool loadv = true;
    const float* Arow = x;
    if (MODE == 0) Arow = x + (size_t)(m0 + a_m) * Kdim;
    else {
        int r = m0 + a_m;
        if (r < cnt) {
            int enc = d_list[z][r];
            Arow = (MODE == 1) ? x + (size_t)(enc >> 1) * Kdim
                               : d_yw + (size_t)enc * Kdim;
        } else loadv = false;
    }
    const float* Brow = Bp + (size_t)b_k * N + n0 + b_n;

    float4 rA0, rA1, rB0, rB1;
    const int NK = Kdim >> 4;
    u64t acc[4][4] = {};

    // prologue: stage 0
    if (loadv) { rA0 = *(const float4*)(Arow + a_k); rA1 = *(const float4*)(Arow + a_k + 4); }
    else       { rA0 = rA1 = make_float4(0.f,0.f,0.f,0.f); }
    rB0 = *(const float4*)(Brow);
    rB1 = *(const float4*)(Brow + 4);
    {
        As[0][a_k+0][a_m]=rA0.x; As[0][a_k+1][a_m]=rA0.y; As[0][a_k+2][a_m]=rA0.z; As[0][a_k+3][a_m]=rA0.w;
        As[0][a_k+4][a_m]=rA1.x; As[0][a_k+5][a_m]=rA1.y; As[0][a_k+6][a_m]=rA1.z; As[0][a_k+7][a_m]=rA1.w;
        *(float4*)&Bs[0][b_k][b_n] = rB0;
        *(float4*)&Bs[0][b_k][b_n+4] = rB1;
    }
    __syncthreads();

    for (int kt = 0; kt < NK; kt++) {
        const int cur = kt & 1;
        const bool more = (kt + 1 < NK);
        if (more) {
            int k0 = (kt + 1) << 4;
            if (loadv) { rA0 = *(const float4*)(Arow + k0 + a_k); rA1 = *(const float4*)(Arow + k0 + a_k + 4); }
            rB0 = *(const float4*)(Brow + (size_t)k0 * N);
            rB1 = *(const float4*)(Brow + (size_t)k0 * N + 4);
        }
        mk16(As[cur], Bs[cur], acc, ty, tx);
        if (more) {
            const int nxt = cur ^ 1;
            As[nxt][a_k+0][a_m]=rA0.x; As[nxt][a_k+1][a_m]=rA0.y; As[nxt][a_k+2][a_m]=rA0.z; As[nxt][a_k+3][a_m]=rA0.w;
            As[nxt][a_k+4][a_m]=rA1.x; As[nxt][a_k+5][a_m]=rA1.y; As[nxt][a_k+6][a_m]=rA1.z; As[nxt][a_k+7][a_m]=rA1.w;
            *(float4*)&Bs[nxt][b_k][b_n] = rB0;
            *(float4*)&Bs[nxt][b_k][b_n+4] = rB1;
            __syncthreads();
        }
    }

    float vals[8][4];
    unpack_acc(acc, vals);

    float4 bias4 = make_float4(0.f,0.f,0.f,0.f);
    if (MODE == 0) bias4 = *(const float4*)(bias + n0 + tx * 4);

#pragma unroll
    for (int i = 0; i < 8; i++) {
        int r = m0 + ty * 8 + i;
        if (MODE != 0 && r >= cnt) continue;
        if (MODE == 0) {
            float* crow = (z ? d_v : d_k) + (size_t)r * N + n0 + tx * 4;
            *(float4*)crow = make_float4(vals[i][0] + bias4.x, vals[i][1] + bias4.y,
                                         vals[i][2] + bias4.z, vals[i][3] + bias4.w);
        } else if (MODE == 1) {
            int enc2 = d_list[z][r];
            float* crow = d_q + (size_t)enc2 * N + n0 + tx * 4;
            *(float4*)crow = make_float4(vals[i][0], vals[i][1], vals[i][2], vals[i][3]);
        } else {
            int enc2 = d_list[z][r];
            float* crow = Cext + (size_t)(enc2 >> 1) * N + n0 + tx * 4;
            atomicAdd(&crow[0], vals[i][0]);
            atomicAdd(&crow[1], vals[i][1]);
            atomicAdd(&crow[2], vals[i][2]);
            atomicAdd(&crow[3], vals[i][3]);
        }
    }
}

// ======== attention logits: S = Q K^T / sqrt(HS), 64x64 causal tiles =========
__global__ __launch_bounds__(128) void attn_qk() {
    const int jt = blockIdx.x, it = blockIdx.y, bb = blockIdx.z;
    if (jt > it) return;
    const int b = bb >> 4, kk = (bb >> 3) & 1, h = bb & 7;

    __shared__ float As[2][16][72];   // [d][i]
    __shared__ float Bs[2][16][72];   // [d][j]

    const int tid = threadIdx.x;
    const int a_m = tid >> 1;
    const int a_k = (tid & 1) << 3;
    const int ty  = tid >> 4;
    const int tx  = tid & 15;

    const float* qrow = d_q + ((size_t)(b * Tc + it * 64 + a_m) * 2 + kk) * AHc + h * HSc;
    const float* krow = d_k + (size_t)(b * Tc + jt * 64 + a_m) * AHc + h * HSc;

    float4 rA0, rA1, rB0, rB1;
    u64t acc[4][4] = {};
    const int NK = HSc >> 4;   // 8

    rA0 = *(const float4*)(qrow + a_k); rA1 = *(const float4*)(qrow + a_k + 4);
    rB0 = *(const float4*)(krow + a_k); rB1 = *(const float4*)(krow + a_k + 4);
    {
        As[0][a_k+0][a_m]=rA0.x; As[0][a_k+1][a_m]=rA0.y; As[0][a_k+2][a_m]=rA0.z; As[0][a_k+3][a_m]=rA0.w;
        As[0][a_k+4][a_m]=rA1.x; As[0][a_k+5][a_m]=rA1.y; As[0][a_k+6][a_m]=rA1.z; As[0][a_k+7][a_m]=rA1.w;
        Bs[0][a_k+0][a_m]=rB0.x; Bs[0][a_k+1][a_m]=rB0.y; Bs[0][a_k+2][a_m]=rB0.z; Bs[0][a_k+3][a_m]=rB0.w;
        Bs[0][a_k+4][a_m]=rB1.x; Bs[0][a_k+5][a_m]=rB1.y; Bs[0][a_k+6][a_m]=rB1.z; Bs[0][a_k+7][a_m]=rB1.w;
    }
    __syncthreads();

    for (int kt = 0; kt < NK; kt++) {
        const int cur = kt & 1;
        const bool more = (kt + 1 < NK);
        if (more) {
            int k0 = (kt + 1) << 4;
            rA0 = *(const float4*)(qrow + k0 + a_k); rA1 = *(const float4*)(qrow + k0 + a_k + 4);
            rB0 = *(const float4*)(krow + k0 + a_k); rB1 = *(const float4*)(krow + k0 + a_k + 4);
        }
        mk16(As[cur], Bs[cur], acc, ty, tx);
        if (more) {
            const int nxt = cur ^ 1;
            As[nxt][a_k+0][a_m]=rA0.x; As[nxt][a_k+1][a_m]=rA0.y; As[nxt][a_k+2][a_m]=rA0.z; As[nxt][a_k+3][a_m]=rA0.w;
            As[nxt][a_k+4][a_m]=rA1.x; As[nxt][a_k+5][a_m]=rA1.y; As[nxt][a_k+6][a_m]=rA1.z; As[nxt][a_k+7][a_m]=rA1.w;
            Bs[nxt][a_k+0][a_m]=rB0.x; Bs[nxt][a_k+1][a_m]=rB0.y; Bs[nxt][a_k+2][a_m]=rB0.z; Bs[nxt][a_k+3][a_m]=rB0.w;
            Bs[nxt][a_k+4][a_m]=rB1.x; Bs[nxt][a_k+5][a_m]=rB1.y; Bs[nxt][a_k+6][a_m]=rB1.z; Bs[nxt][a_k+7][a_m]=rB1.w;
            __syncthreads();
        }
    }

    float vals[8][4];
    unpack_acc(acc, vals);

    const float scale = 0.08838834764831845f; // 1/sqrt(128)
    float* obase = d_att + (size_t)bb * (Tc * Tc) + (size_t)(it * 64) * Tc + jt * 64;
#pragma unroll
    for (int i = 0; i < 8; i++) {
        float* crow = obase + (size_t)(ty * 8 + i) * Tc + tx * 4;
        *(float4*)crow = make_float4(vals[i][0] * scale, vals[i][1] * scale,
                                     vals[i][2] * scale, vals[i][3] * scale);
    }
}

// ---------------- stick-breaking transform, in place (parallel scan) ----------
__device__ __forceinline__ float logsig(float a) {
    return (a >= 0.f) ? -__logf(1.f + __expf(-a)) : (a - __logf(1.f + __expf(a)));
}

__global__ __launch_bounds__(256) void stickbreak() {
    const int row = blockIdx.x;
    const int bb = row >> 9;
    const int i = row & (Tc - 1);
    float* ap = d_att + (size_t)bb * (Tc * Tc) + (size_t)i * Tc;
    const int tid = threadIdx.x;
    const int j0 = tid * 2, j1 = tid * 2 + 1;
    const bool v0 = (j0 <= i), v1 = (j1 <= i);

    float lz0 = 0.f, lb0 = 0.f, lz1 = 0.f, lb1 = 0.f;
    if (v0) { float a = ap[j0]; lz0 = logsig(a); lb0 = lz0 - a; }
    if (v1) { float a = ap[j1]; lz1 = logsig(a); lb1 = lz1 - a; }

    __shared__ float sc[256];
    float s = lb0 + lb1;
    sc[tid] = s; __syncthreads();
#pragma unroll
    for (int off = 1; off < 256; off <<= 1) {
        float t = (tid >= off) ? sc[tid - off] : 0.f;
        __syncthreads();
        sc[tid] += t;
        __syncthreads();
    }
    const float total = sc[255];
    const float excl = sc[tid] - s;
    float w0 = v0 ? __expf(lz0 + (total - (excl + lb0))) : 0.f;
    float w1 = v1 ? __expf(lz1 + (total - (excl + lb0 + lb1))) : 0.f;
    ap[j0] = w0; ap[j1] = w1;
}

// ======== y = att @ V, gate-scaled, 64x64 tiles, causal k skip ========
__global__ __launch_bounds__(128) void attn_av() {
    const int nt = blockIdx.x, it = blockIdx.y, bb = blockIdx.z;
    const int b = bb >> 4, kk = (bb >> 3) & 1, h = bb & 7;
    const int n0 = nt * 64;

    __shared__ float As[2][16][72];
    __shared__ float Bs[2][16][72];

    const int tid = threadIdx.x;
    const int a_m = tid >> 1;
    const int a_k = (tid & 1) << 3;
    const int b_k = tid >> 3;
    const int b_n = (tid & 7) << 3;
    const int ty  = tid >> 4;
    const int tx  = tid & 15;

    const float* arow = d_att + (size_t)bb * (Tc * Tc) + (size_t)(it * 64 + a_m) * Tc;
    const float* vrow = d_v + (size_t)(b * Tc + b_k) * AHc + h * HSc + n0 + b_n;

    float4 rA0, rA1, rB0, rB1;
    u64t acc[4][4] = {};
    const int NK = (it + 1) * 4;   // kmax/16

    rA0 = *(const float4*)(arow + a_k); rA1 = *(const float4*)(arow + a_k + 4);
    rB0 = *(const float4*)(vrow);       rB1 = *(const float4*)(vrow + 4);
    {
        As[0][a_k+0][a_m]=rA0.x; As[0][a_k+1][a_m]=rA0.y; As[0][a_k+2][a_m]=rA0.z; As[0][a_k+3][a_m]=rA0.w;
        As[0][a_k+4][a_m]=rA1.x; As[0][a_k+5][a_m]=rA1.y; As[0][a_k+6][a_m]=rA1.z; As[0][a_k+7][a_m]=rA1.w;
        *(float4*)&Bs[0][b_k][b_n] = rB0;
        *(float4*)&Bs[0][b_k][b_n+4] = rB1;
    }
    __syncthreads();

    for (int kt = 0; kt < NK; kt++) {
        const int cur = kt & 1;
        const bool more = (kt + 1 < NK);
        if (more) {
            int k0 = (kt + 1) << 4;
            rA0 = *(const float4*)(arow + k0 + a_k); rA1 = *(const float4*)(arow + k0 + a_k + 4);
            rB0 = *(const float4*)(vrow + (size_t)k0 * AHc);
            rB1 = *(const float4*)(vrow + (size_t)k0 * AHc + 4);
        }
        mk16(As[cur], Bs[cur], acc, ty, tx);
        if (more) {
            const int nxt = cur ^ 1;
            As[nxt][a_k+0][a_m]=rA0.x; As[nxt][a_k+1][a_m]=rA0.y; As[nxt][a_k+2][a_m]=rA0.z; As[nxt][a_k+3][a_m]=rA0.w;
            As[nxt][a_k+4][a_m]=rA1.x; As[nxt][a_k+5][a_m]=rA1.y; As[nxt][a_k+6][a_m]=rA1.z; As[nxt][a_k+7][a_m]=rA1.w;
            *(float4*)&Bs[nxt][b_k][b_n] = rB0;
            *(float4*)&Bs[nxt][b_k][b_n+4] = rB1;
            __syncthreads();
        }
    }

    float vals[8][4];
    unpack_acc(acc, vals);

#pragma unroll
    for (int i = 0; i < 8; i++) {
        int token = b * Tc + it * 64 + ty * 8 + i;
        float g = d_gates[token * 2 + kk];
        float* yrow = d_yw + ((size_t)token * 2 + kk) * AHc + h * HSc + n0 + tx * 4;
        *(float4*)yrow = make_float4(vals[i][0] * g, vals[i][1] * g,
                                     vals[i][2] * g, vals[i][3] * g);
    }
}

// ---------------- launch ----------------
extern "C" void kernel_launch(void* const* d_in, const int* in_sizes, int n_in,
                              void* d_out, int out_size) {
    const float* x     = (const float*)d_in[0];
    const float* Wg    = (const float*)d_in[1];
    const float* W_in  = (const float*)d_in[2];
    const float* W_out = (const float*)d_in[3];
    const float* Wk    = (const float*)d_in[4];
    const float* bk    = (const float*)d_in[5];
    const float* Wv    = (const float*)d_in[6];
    const float* bv    = (const float*)d_in[7];
    float* out = (float*)d_out;

    zero_kernel<<<(NTOK * Cc + 255) / 256, 256>>>(out);
    gate_kernel<<<(NTOK * 32 + 127) / 128, 128>>>(x, Wg);

    // K and V projections fused into one launch (z selects)
    gemm_db<0><<<dim3(16, 16, 2), 128>>>(x, Wk, bk, Wv, bv, nullptr, AHc, Cc);

    // grouped q projection
    gemm_db<1><<<dim3(16, 16, Ec), 128>>>(x, W_in, nullptr, nullptr, nullptr, nullptr, AHc, Cc);

    // attention logits (causal 64x64 tiles)
    attn_qk<<<dim3(8, 8, NBATCH), 128>>>();

    // stick-breaking weights in place
    stickbreak<<<NBATCH * Tc, 256>>>();

    // y = att @ V, gate scaled
    attn_av<<<dim3(2, 8, NBATCH), 128>>>();

    // grouped output projection, scatter-add into out
    gemm_db<2><<<dim3(16, 16, Ec), 128>>>(nullptr, W_out, nullptr, nullptr, nullptr, out, Cc, AHc);

    // aux loss scalar
    aux_kernel<<<1, 256>>>(out, out_size);
}

// round 16
// speedup vs baseline: 1.8598x; 1.5523x over previous
#include <cuda_runtime.h>
#include <cuda_bf16.h>
#include <math.h>

// Problem constants
#define Bc 2
#define Tc 512
#define Cc 1024
#define Ec 8
#define KTOP 2
#define NHc 8
#define HSc 128
#define AHc 1024
#define NTOK 1024      // B*T
#define NBATCH 32      // B*KTOP*NH

typedef unsigned short ush;
typedef unsigned int u32;

// ---------------- scratch (static device globals; NEVER passed from host) ----
__device__ __align__(256) float d_q  [(size_t)NTOK*KTOP*AHc];
__device__ __align__(256) float d_k  [(size_t)NTOK*AHc];
__device__ __align__(256) float d_v  [(size_t)NTOK*AHc];
__device__ __align__(256) float d_att[(size_t)NBATCH*Tc*Tc];
__device__ __align__(256) float d_yw [(size_t)NTOK*KTOP*AHc];
__device__ float d_gates[NTOK*KTOP];
__device__ float d_probs[NTOK*Ec];
__device__ int   d_cnt [Ec];
__device__ int   d_list[Ec][NTOK];

// bf16 hi/lo split scratch
__device__ __align__(256) ush g_xh  [(size_t)NTOK*Cc];
__device__ __align__(256) ush g_xl  [(size_t)NTOK*Cc];
__device__ __align__(256) ush g_wkh [(size_t)Cc*AHc];
__device__ __align__(256) ush g_wkl [(size_t)Cc*AHc];
__device__ __align__(256) ush g_wvh [(size_t)Cc*AHc];
__device__ __align__(256) ush g_wvl [(size_t)Cc*AHc];
__device__ __align__(256) ush g_winh[(size_t)Ec*Cc*AHc];
__device__ __align__(256) ush g_winl[(size_t)Ec*Cc*AHc];
__device__ __align__(256) ush g_wouth[(size_t)Ec*AHc*Cc];
__device__ __align__(256) ush g_woutl[(size_t)Ec*AHc*Cc];
__device__ __align__(256) ush g_ywh [(size_t)NTOK*KTOP*AHc];
__device__ __align__(256) ush g_ywl [(size_t)NTOK*KTOP*AHc];

// ---------------- mma / ldmatrix helpers ----------------
__device__ __forceinline__ u32 smaddr(const void* p) {
    return (u32)__cvta_generic_to_shared(p);
}
__device__ __forceinline__ void ldsm4(u32& r0, u32& r1, u32& r2, u32& r3, u32 a) {
    asm volatile("ldmatrix.sync.aligned.m8n8.x4.shared.b16 {%0,%1,%2,%3}, [%4];"
                 : "=r"(r0), "=r"(r1), "=r"(r2), "=r"(r3) : "r"(a));
}
__device__ __forceinline__ void ldsm4t(u32& r0, u32& r1, u32& r2, u32& r3, u32 a) {
    asm volatile("ldmatrix.sync.aligned.m8n8.x4.trans.shared.b16 {%0,%1,%2,%3}, [%4];"
                 : "=r"(r0), "=r"(r1), "=r"(r2), "=r"(r3) : "r"(a));
}
__device__ __forceinline__ void mma_bf16(float (&c)[4], const u32 (&A)[4], u32 b0, u32 b1) {
    asm volatile(
        "mma.sync.aligned.m16n8k16.row.col.f32.bf16.bf16.f32 "
        "{%0,%1,%2,%3}, {%4,%5,%6,%7}, {%8,%9}, {%0,%1,%2,%3};"
        : "+f"(c[0]), "+f"(c[1]), "+f"(c[2]), "+f"(c[3])
        : "r"(A[0]), "r"(A[1]), "r"(A[2]), "r"(A[3]), "r"(b0), "r"(b1));
}

// ---------------- f32x2 helpers (attention kernels) ----------------
typedef unsigned long long u64t;
__device__ __forceinline__ u64t pk2(float lo, float hi) {
    u64t r; asm("mov.b64 %0, {%1, %2};" : "=l"(r) : "f"(lo), "f"(hi)); return r;
}
__device__ __forceinline__ u64t splat2(float v) {
    u64t r; asm("mov.b64 %0, {%1, %1};" : "=l"(r) : "f"(v)); return r;
}
__device__ __forceinline__ void upk2(u64t v, float& lo, float& hi) {
    asm("mov.b64 {%0, %1}, %2;" : "=f"(lo), "=f"(hi) : "l"(v));
}
__device__ __forceinline__ void fma2(u64t& d, u64t a, u64t b) {
    asm("fma.rn.f32x2 %0, %1, %2, %3;" : "=l"(d) : "l"(a), "l"(b), "l"(d));
}
__device__ __forceinline__ void mk16(const float (*__restrict__ As)[72],
                                     const float (*__restrict__ Bs)[72],
                                     u64t (&acc)[4][4], int ty, int tx)
{
#pragma unroll
    for (int k = 0; k < 16; k++) {
        float4 aL = *(const float4*)&As[k][ty * 8];
        float4 aH = *(const float4*)&As[k][ty * 8 + 4];
        float4 bV = *(const float4*)&Bs[k][tx * 4];
        u64t a0 = pk2(aL.x, aL.y), a1 = pk2(aL.z, aL.w);
        u64t a2 = pk2(aH.x, aH.y), a3 = pk2(aH.z, aH.w);
        u64t b0 = splat2(bV.x), b1 = splat2(bV.y), b2 = splat2(bV.z), b3 = splat2(bV.w);
        fma2(acc[0][0], a0, b0); fma2(acc[0][1], a0, b1); fma2(acc[0][2], a0, b2); fma2(acc[0][3], a0, b3);
        fma2(acc[1][0], a1, b0); fma2(acc[1][1], a1, b1); fma2(acc[1][2], a1, b2); fma2(acc[1][3], a1, b3);
        fma2(acc[2][0], a2, b0); fma2(acc[2][1], a2, b1); fma2(acc[2][2], a2, b2); fma2(acc[2][3], a2, b3);
        fma2(acc[3][0], a3, b0); fma2(acc[3][1], a3, b1); fma2(acc[3][2], a3, b2); fma2(acc[3][3], a3, b3);
    }
}
__device__ __forceinline__ void unpack_acc(u64t (&acc)[4][4], float (&vals)[8][4]) {
#pragma unroll
    for (int p = 0; p < 4; p++)
#pragma unroll
        for (int j = 0; j < 4; j++)
            upk2(acc[p][j], vals[2 * p][j], vals[2 * p + 1][j]);
}

// ---------------- zero init ----------------
__global__ void zero_kernel(float* __restrict__ out) {
    int i = blockIdx.x * blockDim.x + threadIdx.x;
    if (i < NTOK * Cc) out[i] = 0.f;
    if (i < Ec) d_cnt[i] = 0;
}

// ---------------- gating: warp per token ----------------
__global__ void gate_kernel(const float* __restrict__ x, const float* __restrict__ Wg) {
    int warp = (blockIdx.x * blockDim.x + threadIdx.x) >> 5;
    int lane = threadIdx.x & 31;
    if (warp >= NTOK) return;
    const float* xr = x + (size_t)warp * Cc;
    float acc[Ec];
#pragma unroll
    for (int e = 0; e < Ec; e++) acc[e] = 0.f;
    for (int c = lane; c < Cc; c += 32) {
        float xv = xr[c];
        const float* w = Wg + (size_t)c * Ec;
#pragma unroll
        for (int e = 0; e < Ec; e++) acc[e] += xv * w[e];
    }
#pragma unroll
    for (int off = 16; off; off >>= 1)
#pragma unroll
        for (int e = 0; e < Ec; e++) acc[e] += __shfl_down_sync(0xffffffffu, acc[e], off);

    if (lane == 0) {
        float v1 = -1e30f, v2 = -1e30f; int i1 = 0, i2 = 0;
#pragma unroll
        for (int e = 0; e < Ec; e++) {
            float a = acc[e];
            if (a > v1)      { v2 = v1; i2 = i1; v1 = a; i1 = e; }
            else if (a > v2) { v2 = a; i2 = e; }
        }
        float g1 = 1.f / (1.f + expf(v2 - v1));
        d_gates[warp * 2 + 0] = g1;
        d_gates[warp * 2 + 1] = 1.f - g1;
        float s = 0.f, ex[Ec];
#pragma unroll
        for (int e = 0; e < Ec; e++) { ex[e] = expf(acc[e] - v1); s += ex[e]; }
        float inv = 1.f / s;
#pragma unroll
        for (int e = 0; e < Ec; e++) d_probs[warp * Ec + e] = ex[e] * inv;
        int p0 = atomicAdd(&d_cnt[i1], 1); d_list[i1][p0] = (warp << 1) | 0;
        int p1 = atomicAdd(&d_cnt[i2], 1); d_list[i2][p1] = (warp << 1) | 1;
    }
}

// ---------------- aux loss ----------------
__global__ void aux_kernel(float* __restrict__ out, int out_size) {
    __shared__ float sh[256];
    int tid = threadIdx.x;
    float aux = 0.f;
    for (int e = 0; e < Ec; e++) {
        float s = 0.f;
        for (int t = tid; t < NTOK; t += 256) s += d_probs[t * Ec + e];
        sh[tid] = s; __syncthreads();
        for (int off = 128; off; off >>= 1) {
            if (tid < off) sh[tid] += sh[tid + off];
            __syncthreads();
        }
        if (tid == 0) aux += (sh[0] / (float)NTOK) * ((float)d_cnt[e] / (float)NTOK);
        __syncthreads();
    }
    if (tid == 0 && out_size > NTOK * Cc) out[out_size - 1] = (float)Ec * aux;
}

// ---------------- bf16 hi/lo split conversion ----------------
// DST: 0=x, 1=Wk, 2=Wv, 3=Win, 4=Wout, 5=yw (reads d_yw internally)
template<int DST>
__global__ void cvt_split(const float* __restrict__ src, int n) {
    int i4 = blockIdx.x * blockDim.x + threadIdx.x;
    if (i4 * 4 >= n) return;
    const float* sp;
    if (DST == 5) sp = d_yw; else sp = src;
    float4 v = ((const float4*)sp)[i4];
    ush* ph; ush* pl;
    if (DST == 0)      { ph = g_xh;    pl = g_xl;    }
    else if (DST == 1) { ph = g_wkh;   pl = g_wkl;   }
    else if (DST == 2) { ph = g_wvh;   pl = g_wvl;   }
    else if (DST == 3) { ph = g_winh;  pl = g_winl;  }
    else if (DST == 4) { ph = g_wouth; pl = g_woutl; }
    else               { ph = g_ywh;   pl = g_ywl;   }
    __nv_bfloat16 hx = __float2bfloat16_rn(v.x);
    __nv_bfloat16 hy = __float2bfloat16_rn(v.y);
    __nv_bfloat16 hz = __float2bfloat16_rn(v.z);
    __nv_bfloat16 hw = __float2bfloat16_rn(v.w);
    __nv_bfloat16 lx = __float2bfloat16_rn(v.x - __bfloat162float(hx));
    __nv_bfloat16 ly = __float2bfloat16_rn(v.y - __bfloat162float(hy));
    __nv_bfloat16 lz = __float2bfloat16_rn(v.z - __bfloat162float(hz));
    __nv_bfloat16 lw = __float2bfloat16_rn(v.w - __bfloat162float(hw));
    ush hh[4] = { __bfloat16_as_ushort(hx), __bfloat16_as_ushort(hy),
                  __bfloat16_as_ushort(hz), __bfloat16_as_ushort(hw) };
    ush ll[4] = { __bfloat16_as_ushort(lx), __bfloat16_as_ushort(ly),
                  __bfloat16_as_ushort(lz), __bfloat16_as_ushort(lw) };
    *(uint2*)(ph + (size_t)i4 * 4) = *(const uint2*)hh;
    *(uint2*)(pl + (size_t)i4 * 4) = *(const uint2*)ll;
}

// ========== bf16x2 tensor-core GEMM: 128x64 tile, kc=32, 256 threads =========
// C = Ah@Bh + Ah@Bl + Al@Bh  (fp32 accum)  -> ~fp32 accuracy
// MODE 0: dense. z=0: x@Wk+bk->d_k ; z=1: x@Wv+bv->d_v
// MODE 1: grouped q (gather x rows via d_list[z]) -> d_q
// MODE 2: grouped out (yw rows via d_list[z]) -> atomicAdd Cext
template<int MODE>
__global__ __launch_bounds__(256) void gemm_t(
    const float* __restrict__ bias_k, const float* __restrict__ bias_v,
    float* __restrict__ Cext)
{
    const int z = blockIdx.z;
    const int cnt = (MODE == 0) ? NTOK : d_cnt[z];
    const int m0 = blockIdx.y * 128;
    if (m0 >= cnt) return;
    const int n0 = blockIdx.x * 64;
    const int K = 1024, N = 1024;

    const ush *Bh, *Bl;
    if (MODE == 0) { Bh = z ? g_wvh : g_wkh; Bl = z ? g_wvl : g_wkl; }
    else if (MODE == 1) { Bh = g_winh + (size_t)z * K * N; Bl = g_winl + (size_t)z * K * N; }
    else { Bh = g_wouth + (size_t)z * K * N; Bl = g_woutl + (size_t)z * K * N; }

    __shared__ __align__(16) ush As_h[128][40];
    __shared__ __align__(16) ush As_l[128][40];
    __shared__ __align__(16) ush Bs_h[32][88];
    __shared__ __align__(16) ush Bs_l[32][88];

    const int tid = threadIdx.x;
    const int lane = tid & 31;
    const int warp = tid >> 5;
    const int wm = warp >> 1;        // 0..3
    const int wn = warp & 1;         // 0..1

    const int s_row = tid >> 1;               // 0..127 (A row)
    const int s_half = (tid & 1) * 16;        // A col offset
    const int s_kr = tid >> 3;                // 0..31 (B k-row)
    const int s_no = (tid & 7) * 8;           // B n offset

    bool loadv = true;
    const ush *Arh = g_xh, *Arl = g_xl;
    if (MODE == 0) {
        Arh = g_xh + (size_t)(m0 + s_row) * K;
        Arl = g_xl + (size_t)(m0 + s_row) * K;
    } else {
        int r = m0 + s_row;
        if (r < cnt) {
            int enc = d_list[z][r];
            if (MODE == 1) {
                Arh = g_xh + (size_t)(enc >> 1) * K;
                Arl = g_xl + (size_t)(enc >> 1) * K;
            } else {
                Arh = g_ywh + (size_t)enc * K;
                Arl = g_ywl + (size_t)enc * K;
            }
        } else loadv = false;
    }
    const ush* Brh = Bh + (size_t)s_kr * N + n0 + s_no;
    const ush* Brl = Bl + (size_t)s_kr * N + n0 + s_no;

    float acc[2][4][4] = {};

    for (int k0 = 0; k0 < K; k0 += 32) {
        uint4 va0, va1, vb0, vb1;
        if (loadv) {
            va0 = *(const uint4*)(Arh + k0 + s_half);
            va1 = *(const uint4*)(Arh + k0 + s_half + 8);
            vb0 = *(const uint4*)(Arl + k0 + s_half);
            vb1 = *(const uint4*)(Arl + k0 + s_half + 8);
        } else {
            va0 = va1 = vb0 = vb1 = make_uint4(0, 0, 0, 0);
        }
        *(uint4*)&As_h[s_row][s_half]     = va0;
        *(uint4*)&As_h[s_row][s_half + 8] = va1;
        *(uint4*)&As_l[s_row][s_half]     = vb0;
        *(uint4*)&As_l[s_row][s_half + 8] = vb1;
        *(uint4*)&Bs_h[s_kr][s_no] = *(const uint4*)(Brh + (size_t)k0 * N);
        *(uint4*)&Bs_l[s_kr][s_no] = *(const uint4*)(Brl + (size_t)k0 * N);
        __syncthreads();

#pragma unroll
        for (int kc = 0; kc < 2; kc++) {
            u32 Ah[2][4], Al[2][4];
            {
                int rowa = wm * 32 + (lane & 7) + ((lane >> 3) & 1) * 8;
                int cola = kc * 16 + (lane >> 4) * 8;
#pragma unroll
                for (int mt = 0; mt < 2; mt++) {
                    u32 ad = smaddr(&As_h[rowa + mt * 16][cola]);
                    ldsm4(Ah[mt][0], Ah[mt][1], Ah[mt][2], Ah[mt][3], ad);
                    u32 ad2 = smaddr(&As_l[rowa + mt * 16][cola]);
                    ldsm4(Al[mt][0], Al[mt][1], Al[mt][2], Al[mt][3], ad2);
                }
            }
            u32 Bhf[2][4], Blf[2][4];
            {
                int kb = kc * 16 + (lane & 7) + ((lane >> 3) & 1) * 8;
                int cb0 = wn * 32 + (lane >> 4) * 8;
#pragma unroll
                for (int np = 0; np < 2; np++) {
                    u32 bd = smaddr(&Bs_h[kb][cb0 + np * 16]);
                    ldsm4t(Bhf[np][0], Bhf[np][1], Bhf[np][2], Bhf[np][3], bd);
                    u32 bd2 = smaddr(&Bs_l[kb][cb0 + np * 16]);
                    ldsm4t(Blf[np][0], Blf[np][1], Blf[np][2], Blf[np][3], bd2);
                }
            }
#pragma unroll
            for (int mt = 0; mt < 2; mt++) {
#pragma unroll
                for (int nt = 0; nt < 4; nt++) {
                    int np = nt >> 1;
                    int hi = (nt & 1) * 2;
                    mma_bf16(acc[mt][nt], Ah[mt], Bhf[np][hi], Bhf[np][hi + 1]);
                    mma_bf16(acc[mt][nt], Ah[mt], Blf[np][hi], Blf[np][hi + 1]);
                    mma_bf16(acc[mt][nt], Al[mt], Bhf[np][hi], Bhf[np][hi + 1]);
                }
            }
        }
        __syncthreads();
    }

    const int g = lane >> 2;
    const int tc = (lane & 3) * 2;
    const float* bias = (MODE == 0) ? (z ? bias_v : bias_k) : nullptr;

#pragma unroll
    for (int mt = 0; mt < 2; mt++) {
#pragma unroll
        for (int nt = 0; nt < 4; nt++) {
            int col = n0 + wn * 32 + nt * 8 + tc;
            int rt0 = wm * 32 + mt * 16 + g;
#pragma unroll
            for (int half = 0; half < 2; half++) {
                int rt = rt0 + half * 8;
                int r = m0 + rt;
                float c0 = acc[mt][nt][half * 2 + 0];
                float c1 = acc[mt][nt][half * 2 + 1];
                if (MODE == 0) {
                    float* dst = (z ? d_v : d_k) + (size_t)r * 1024 + col;
                    dst[0] = c0 + bias[col];
                    dst[1] = c1 + bias[col + 1];
                } else if (r < cnt) {
                    int enc = d_list[z][r];
                    if (MODE == 1) {
                        float* dst = d_q + (size_t)enc * 1024 + col;
                        dst[0] = c0; dst[1] = c1;
                    } else {
                        float* dst = Cext + (size_t)(enc >> 1) * 1024 + col;
                        atomicAdd(&dst[0], c0);
                        atomicAdd(&dst[1], c1);
                    }
                }
            }
        }
    }
}

// ======== attention logits: S = Q K^T / sqrt(HS), 64x64 causal tiles =========
__global__ __launch_bounds__(128) void attn_qk() {
    const int jt = blockIdx.x, it = blockIdx.y, bb = blockIdx.z;
    if (jt > it) return;
    const int b = bb >> 4, kk = (bb >> 3) & 1, h = bb & 7;

    __shared__ float As[2][16][72];
    __shared__ float Bs[2][16][72];

    const int tid = threadIdx.x;
    const int a_m = tid >> 1;
    const int a_k = (tid & 1) << 3;
    const int ty  = tid >> 4;
    const int tx  = tid & 15;

    const float* qrow = d_q + ((size_t)(b * Tc + it * 64 + a_m) * 2 + kk) * AHc + h * HSc;
    const float* krow = d_k + (size_t)(b * Tc + jt * 64 + a_m) * AHc + h * HSc;

    float4 rA0, rA1, rB0, rB1;
    u64t acc[4][4] = {};
    const int NK = HSc >> 4;

    rA0 = *(const float4*)(qrow + a_k); rA1 = *(const float4*)(qrow + a_k + 4);
    rB0 = *(const float4*)(krow + a_k); rB1 = *(const float4*)(krow + a_k + 4);
    {
        As[0][a_k+0][a_m]=rA0.x; As[0][a_k+1][a_m]=rA0.y; As[0][a_k+2][a_m]=rA0.z; As[0][a_k+3][a_m]=rA0.w;
        As[0][a_k+4][a_m]=rA1.x; As[0][a_k+5][a_m]=rA1.y; As[0][a_k+6][a_m]=rA1.z; As[0][a_k+7][a_m]=rA1.w;
        Bs[0][a_k+0][a_m]=rB0.x; Bs[0][a_k+1][a_m]=rB0.y; Bs[0][a_k+2][a_m]=rB0.z; Bs[0][a_k+3][a_m]=rB0.w;
        Bs[0][a_k+4][a_m]=rB1.x; Bs[0][a_k+5][a_m]=rB1.y; Bs[0][a_k+6][a_m]=rB1.z; Bs[0][a_k+7][a_m]=rB1.w;
    }
    __syncthreads();

    for (int kt = 0; kt < NK; kt++) {
        const int cur = kt & 1;
        const bool more = (kt + 1 < NK);
        if (more) {
            int k0 = (kt + 1) << 4;
            rA0 = *(const float4*)(qrow + k0 + a_k); rA1 = *(const float4*)(qrow + k0 + a_k + 4);
            rB0 = *(const float4*)(krow + k0 + a_k); rB1 = *(const float4*)(krow + k0 + a_k + 4);
        }
        mk16(As[cur], Bs[cur], acc, ty, tx);
        if (more) {
            const int nxt = cur ^ 1;
            As[nxt][a_k+0][a_m]=rA0.x; As[nxt][a_k+1][a_m]=rA0.y; As[nxt][a_k+2][a_m]=rA0.z; As[nxt][a_k+3][a_m]=rA0.w;
            As[nxt][a_k+4][a_m]=rA1.x; As[nxt][a_k+5][a_m]=rA1.y; As[nxt][a_k+6][a_m]=rA1.z; As[nxt][a_k+7][a_m]=rA1.w;
            Bs[nxt][a_k+0][a_m]=rB0.x; Bs[nxt][a_k+1][a_m]=rB0.y; Bs[nxt][a_k+2][a_m]=rB0.z; Bs[nxt][a_k+3][a_m]=rB0.w;
            Bs[nxt][a_k+4][a_m]=rB1.x; Bs[nxt][a_k+5][a_m]=rB1.y; Bs[nxt][a_k+6][a_m]=rB1.z; Bs[nxt][a_k+7][a_m]=rB1.w;
            __syncthreads();
        }
    }

    float vals[8][4];
    unpack_acc(acc, vals);

    const float scale = 0.08838834764831845f;
    float* obase = d_att + (size_t)bb * (Tc * Tc) + (size_t)(it * 64) * Tc + jt * 64;
#pragma unroll
    for (int i = 0; i < 8; i++) {
        float* crow = obase + (size_t)(ty * 8 + i) * Tc + tx * 4;
        *(float4*)crow = make_float4(vals[i][0] * scale, vals[i][1] * scale,
                                     vals[i][2] * scale, vals[i][3] * scale);
    }
}

// ---------------- stick-breaking transform ----------------
__device__ __forceinline__ float logsig(float a) {
    return (a >= 0.f) ? -__logf(1.f + __expf(-a)) : (a - __logf(1.f + __expf(a)));
}

__global__ __launch_bounds__(256) void stickbreak() {
    const int row = blockIdx.x;
    const int bb = row >> 9;
    const int i = row & (Tc - 1);
    float* ap = d_att + (size_t)bb * (Tc * Tc) + (size_t)i * Tc;
    const int tid = threadIdx.x;
    const int j0 = tid * 2, j1 = tid * 2 + 1;
    const bool v0 = (j0 <= i), v1 = (j1 <= i);

    float lz0 = 0.f, lb0 = 0.f, lz1 = 0.f, lb1 = 0.f;
    if (v0) { float a = ap[j0]; lz0 = logsig(a); lb0 = lz0 - a; }
    if (v1) { float a = ap[j1]; lz1 = logsig(a); lb1 = lz1 - a; }

    __shared__ float sc[256];
    float s = lb0 + lb1;
    sc[tid] = s; __syncthreads();
#pragma unroll
    for (int off = 1; off < 256; off <<= 1) {
        float t = (tid >= off) ? sc[tid - off] : 0.f;
        __syncthreads();
        sc[tid] += t;
        __syncthreads();
    }
    const float total = sc[255];
    const float excl = sc[tid] - s;
    float w0 = v0 ? __expf(lz0 + (total - (excl + lb0))) : 0.f;
    float w1 = v1 ? __expf(lz1 + (total - (excl + lb0 + lb1))) : 0.f;
    ap[j0] = w0; ap[j1] = w1;
}

// ======== y = att @ V, gate-scaled, 64x64 tiles, causal k skip ========
__global__ __launch_bounds__(128) void attn_av() {
    const int nt = blockIdx.x, it = blockIdx.y, bb = blockIdx.z;
    const int b = bb >> 4, kk = (bb >> 3) & 1, h = bb & 7;
    const int n0 = nt * 64;

    __shared__ float As[2][16][72];
    __shared__ float Bs[2][16][72];

    const int tid = threadIdx.x;
    const int a_m = tid >> 1;
    const int a_k = (tid & 1) << 3;
    const int b_k = tid >> 3;
    const int b_n = (tid & 7) << 3;
    const int ty  = tid >> 4;
    const int tx  = tid & 15;

    const float* arow = d_att + (size_t)bb * (Tc * Tc) + (size_t)(it * 64 + a_m) * Tc;
    const float* vrow = d_v + (size_t)(b * Tc + b_k) * AHc + h * HSc + n0 + b_n;

    float4 rA0, rA1, rB0, rB1;
    u64t acc[4][4] = {};
    const int NK = (it + 1) * 4;

    rA0 = *(const float4*)(arow + a_k); rA1 = *(const float4*)(arow + a_k + 4);
    rB0 = *(const float4*)(vrow);       rB1 = *(const float4*)(vrow + 4);
    {
        As[0][a_k+0][a_m]=rA0.x; As[0][a_k+1][a_m]=rA0.y; As[0][a_k+2][a_m]=rA0.z; As[0][a_k+3][a_m]=rA0.w;
        As[0][a_k+4][a_m]=rA1.x; As[0][a_k+5][a_m]=rA1.y; As[0][a_k+6][a_m]=rA1.z; As[0][a_k+7][a_m]=rA1.w;
        *(float4*)&Bs[0][b_k][b_n] = rB0;
        *(float4*)&Bs[0][b_k][b_n+4] = rB1;
    }
    __syncthreads();

    for (int kt = 0; kt < NK; kt++) {
        const int cur = kt & 1;
        const bool more = (kt + 1 < NK);
        if (more) {
            int k0 = (kt + 1) << 4;
            rA0 = *(const float4*)(arow + k0 + a_k); rA1 = *(const float4*)(arow + k0 + a_k + 4);
            rB0 = *(const float4*)(vrow + (size_t)k0 * AHc);
            rB1 = *(const float4*)(vrow + (size_t)k0 * AHc + 4);
        }
        mk16(As[cur], Bs[cur], acc, ty, tx);
        if (more) {
            const int nxt = cur ^ 1;
            As[nxt][a_k+0][a_m]=rA0.x; As[nxt][a_k+1][a_m]=rA0.y; As[nxt][a_k+2][a_m]=rA0.z; As[nxt][a_k+3][a_m]=rA0.w;
            As[nxt][a_k+4][a_m]=rA1.x; As[nxt][a_k+5][a_m]=rA1.y; As[nxt][a_k+6][a_m]=rA1.z; As[nxt][a_k+7][a_m]=rA1.w;
            *(float4*)&Bs[nxt][b_k][b_n] = rB0;
            *(float4*)&Bs[nxt][b_k][b_n+4] = rB1;
            __syncthreads();
        }
    }

    float vals[8][4];
    unpack_acc(acc, vals);

#pragma unroll
    for (int i = 0; i < 8; i++) {
        int token = b * Tc + it * 64 + ty * 8 + i;
        float g = d_gates[token * 2 + kk];
        float* yrow = d_yw + ((size_t)token * 2 + kk) * AHc + h * HSc + n0 + tx * 4;
        *(float4*)yrow = make_float4(vals[i][0] * g, vals[i][1] * g,
                                     vals[i][2] * g, vals[i][3] * g);
    }
}

// ---------------- launch ----------------
extern "C" void kernel_launch(void* const* d_in, const int* in_sizes, int n_in,
                              void* d_out, int out_size) {
    const float* x     = (const float*)d_in[0];
    const float* Wg    = (const float*)d_in[1];
    const float* W_in  = (const float*)d_in[2];
    const float* W_out = (const float*)d_in[3];
    const float* Wk    = (const float*)d_in[4];
    const float* bk    = (const float*)d_in[5];
    const float* Wv    = (const float*)d_in[6];
    const float* bv    = (const float*)d_in[7];
    float* out = (float*)d_out;

    zero_kernel<<<(NTOK * Cc + 255) / 256, 256>>>(out);
    gate_kernel<<<(NTOK * 32 + 127) / 128, 128>>>(x, Wg);

    // bf16 hi/lo splits of inputs
    cvt_split<0><<<1024, 256>>>(x, NTOK * Cc);
    cvt_split<1><<<1024, 256>>>(Wk, Cc * AHc);
    cvt_split<2><<<1024, 256>>>(Wv, Cc * AHc);
    cvt_split<3><<<8192, 256>>>(W_in, Ec * Cc * AHc);
    cvt_split<4><<<8192, 256>>>(W_out, Ec * AHc * Cc);

    // K and V projections (tensor, z selects)
    gemm_t<0><<<dim3(16, 8, 2), 256>>>(bk, bv, nullptr);

    // grouped q projection (tensor)
    gemm_t<1><<<dim3(16, 16, Ec), 256>>>(nullptr, nullptr, nullptr);

    // attention logits (fp32, causal 64x64 tiles)
    attn_qk<<<dim3(8, 8, NBATCH), 128>>>();

    // stick-breaking weights in place
    stickbreak<<<NBATCH * Tc, 256>>>();

    // y = att @ V, gate scaled (fp32)
    attn_av<<<dim3(2, 8, NBATCH), 128>>>();

    // split yw, then grouped output projection (tensor) scatter-add into out
    cvt_split<5><<<2048, 256>>>(nullptr, NTOK * KTOP * AHc);
    gemm_t<2><<<dim3(16, 16, Ec), 256>>>(nullptr, nullptr, out);

    // aux loss scalar
    aux_kernel<<<1, 256>>>(out, out_size);
}

// round 17
// speedup vs baseline: 1.9539x; 1.0506x over previous
#include <cuda_runtime.h>
#include <cuda_bf16.h>
#include <math.h>

// Problem constants
#define Bc 2
#define Tc 512
#define Cc 1024
#define Ec 8
#define KTOP 2
#define NHc 8
#define HSc 128
#define AHc 1024
#define NTOK 1024      // B*T
#define NBATCH 32      // B*KTOP*NH

typedef unsigned short ush;
typedef unsigned int u32;

// ---------------- scratch (static device globals; NEVER passed from host) ----
__device__ __align__(256) float d_att[(size_t)NBATCH*Tc*Tc];   // logits (f32)
__device__ float d_gates[NTOK*KTOP];
__device__ float d_probs[NTOK*Ec];
__device__ int   d_cnt [Ec];
__device__ int   d_list[Ec][NTOK];

// bf16 hi/lo split buffers
__device__ __align__(256) ush g_xh  [(size_t)NTOK*Cc];
__device__ __align__(256) ush g_xl  [(size_t)NTOK*Cc];
__device__ __align__(256) ush g_wkh [(size_t)Cc*AHc];
__device__ __align__(256) ush g_wkl [(size_t)Cc*AHc];
__device__ __align__(256) ush g_wvh [(size_t)Cc*AHc];
__device__ __align__(256) ush g_wvl [(size_t)Cc*AHc];
__device__ __align__(256) ush g_winh[(size_t)Ec*Cc*AHc];
__device__ __align__(256) ush g_winl[(size_t)Ec*Cc*AHc];
__device__ __align__(256) ush g_wouth[(size_t)Ec*AHc*Cc];
__device__ __align__(256) ush g_woutl[(size_t)Ec*AHc*Cc];
__device__ __align__(256) ush g_kh  [(size_t)NTOK*AHc];
__device__ __align__(256) ush g_kl  [(size_t)NTOK*AHc];
__device__ __align__(256) ush g_vh  [(size_t)NTOK*AHc];
__device__ __align__(256) ush g_vl  [(size_t)NTOK*AHc];
__device__ __align__(256) ush g_qh  [(size_t)NTOK*KTOP*AHc];
__device__ __align__(256) ush g_ql  [(size_t)NTOK*KTOP*AHc];
__device__ __align__(256) ush g_atth[(size_t)NBATCH*Tc*Tc];
__device__ __align__(256) ush g_attl[(size_t)NBATCH*Tc*Tc];
__device__ __align__(256) ush g_ywh [(size_t)NTOK*KTOP*AHc];
__device__ __align__(256) ush g_ywl [(size_t)NTOK*KTOP*AHc];

// ---------------- mma / ldmatrix helpers ----------------
__device__ __forceinline__ u32 smaddr(const void* p) {
    return (u32)__cvta_generic_to_shared(p);
}
__device__ __forceinline__ void ldsm4(u32& r0, u32& r1, u32& r2, u32& r3, u32 a) {
    asm volatile("ldmatrix.sync.aligned.m8n8.x4.shared.b16 {%0,%1,%2,%3}, [%4];"
                 : "=r"(r0), "=r"(r1), "=r"(r2), "=r"(r3) : "r"(a));
}
__device__ __forceinline__ void ldsm4t(u32& r0, u32& r1, u32& r2, u32& r3, u32 a) {
    asm volatile("ldmatrix.sync.aligned.m8n8.x4.trans.shared.b16 {%0,%1,%2,%3}, [%4];"
                 : "=r"(r0), "=r"(r1), "=r"(r2), "=r"(r3) : "r"(a));
}
__device__ __forceinline__ void mma_bf16(float (&c)[4], const u32 (&A)[4], u32 b0, u32 b1) {
    asm volatile(
        "mma.sync.aligned.m16n8k16.row.col.f32.bf16.bf16.f32 "
        "{%0,%1,%2,%3}, {%4,%5,%6,%7}, {%8,%9}, {%0,%1,%2,%3};"
        : "+f"(c[0]), "+f"(c[1]), "+f"(c[2]), "+f"(c[3])
        : "r"(A[0]), "r"(A[1]), "r"(A[2]), "r"(A[3]), "r"(b0), "r"(b1));
}

// split f32 -> (bf16 hi, bf16 lo)
__device__ __forceinline__ void split_bf16(float v, ush& h, ush& l) {
    __nv_bfloat16 bh = __float2bfloat16_rn(v);
    h = __bfloat16_as_ushort(bh);
    l = __bfloat16_as_ushort(__float2bfloat16_rn(v - __bfloat162float(bh)));
}
__device__ __forceinline__ u32 splitpack(float v0, float v1) {
    ush h0, l0, h1, l1;
    split_bf16(v0, h0, l0);
    split_bf16(v1, h1, l1);
    (void)l0; (void)l1;
    return (u32)h0 | ((u32)h1 << 16);
}

// ---------------- zero init ----------------
__global__ void zero_kernel(float* __restrict__ out) {
    int i = blockIdx.x * blockDim.x + threadIdx.x;
    if (i < NTOK * Cc) out[i] = 0.f;
    if (i < Ec) d_cnt[i] = 0;
}

// ---------------- gating: warp per token ----------------
__global__ void gate_kernel(const float* __restrict__ x, const float* __restrict__ Wg) {
    int warp = (blockIdx.x * blockDim.x + threadIdx.x) >> 5;
    int lane = threadIdx.x & 31;
    if (warp >= NTOK) return;
    const float* xr = x + (size_t)warp * Cc;
    float acc[Ec];
#pragma unroll
    for (int e = 0; e < Ec; e++) acc[e] = 0.f;
    for (int c = lane; c < Cc; c += 32) {
        float xv = xr[c];
        const float* w = Wg + (size_t)c * Ec;
#pragma unroll
        for (int e = 0; e < Ec; e++) acc[e] += xv * w[e];
    }
#pragma unroll
    for (int off = 16; off; off >>= 1)
#pragma unroll
        for (int e = 0; e < Ec; e++) acc[e] += __shfl_down_sync(0xffffffffu, acc[e], off);

    if (lane == 0) {
        float v1 = -1e30f, v2 = -1e30f; int i1 = 0, i2 = 0;
#pragma unroll
        for (int e = 0; e < Ec; e++) {
            float a = acc[e];
            if (a > v1)      { v2 = v1; i2 = i1; v1 = a; i1 = e; }
            else if (a > v2) { v2 = a; i2 = e; }
        }
        float g1 = 1.f / (1.f + expf(v2 - v1));
        d_gates[warp * 2 + 0] = g1;
        d_gates[warp * 2 + 1] = 1.f - g1;
        float s = 0.f, ex[Ec];
#pragma unroll
        for (int e = 0; e < Ec; e++) { ex[e] = expf(acc[e] - v1); s += ex[e]; }
        float inv = 1.f / s;
#pragma unroll
        for (int e = 0; e < Ec; e++) d_probs[warp * Ec + e] = ex[e] * inv;
        int p0 = atomicAdd(&d_cnt[i1], 1); d_list[i1][p0] = (warp << 1) | 0;
        int p1 = atomicAdd(&d_cnt[i2], 1); d_list[i2][p1] = (warp << 1) | 1;
    }
}

// ---------------- aux loss ----------------
__global__ void aux_kernel(float* __restrict__ out, int out_size) {
    __shared__ float sh[256];
    int tid = threadIdx.x;
    float aux = 0.f;
    for (int e = 0; e < Ec; e++) {
        float s = 0.f;
        for (int t = tid; t < NTOK; t += 256) s += d_probs[t * Ec + e];
        sh[tid] = s; __syncthreads();
        for (int off = 128; off; off >>= 1) {
            if (tid < off) sh[tid] += sh[tid + off];
            __syncthreads();
        }
        if (tid == 0) aux += (sh[0] / (float)NTOK) * ((float)d_cnt[e] / (float)NTOK);
        __syncthreads();
    }
    if (tid == 0 && out_size > NTOK * Cc) out[out_size - 1] = (float)Ec * aux;
}

// ---------------- bf16 hi/lo split conversion (4 float4 per thread) ----------
// DST: 0=x, 1=Wk, 2=Wv, 3=Win, 4=Wout
template<int DST>
__global__ void cvt_split(const float* __restrict__ src, int n) {
    ush* ph; ush* pl;
    if (DST == 0)      { ph = g_xh;    pl = g_xl;    }
    else if (DST == 1) { ph = g_wkh;   pl = g_wkl;   }
    else if (DST == 2) { ph = g_wvh;   pl = g_wvl;   }
    else if (DST == 3) { ph = g_winh;  pl = g_winl;  }
    else               { ph = g_wouth; pl = g_woutl; }
    const int stride = gridDim.x * blockDim.x;
    int idx = blockIdx.x * blockDim.x + threadIdx.x;
#pragma unroll
    for (int r = 0; r < 4; r++) {
        int i4 = idx + r * stride;
        if (i4 * 4 < n) {
            float4 v = ((const float4*)src)[i4];
            ush h0, l0, h1, l1, h2, l2, h3, l3;
            split_bf16(v.x, h0, l0); split_bf16(v.y, h1, l1);
            split_bf16(v.z, h2, l2); split_bf16(v.w, h3, l3);
            ush hh[4] = {h0, h1, h2, h3};
            ush ll[4] = {l0, l1, l2, l3};
            *(uint2*)(ph + (size_t)i4 * 4) = *(const uint2*)hh;
            *(uint2*)(pl + (size_t)i4 * 4) = *(const uint2*)ll;
        }
    }
}

// ========== bf16x2 tensor-core GEMM: 128x64 tile, kc=32, 256 threads =========
// C = Ah@Bh + Ah@Bl + Al@Bh  (fp32 accum)
// MODE 0: dense. z=0: x@Wk+bk -> g_kh/g_kl ; z=1: x@Wv+bv -> g_vh/g_vl
// MODE 1: grouped q -> g_qh/g_ql
// MODE 2: grouped out (yw rows) -> atomicAdd Cext (f32)
template<int MODE>
__global__ __launch_bounds__(256) void gemm_t(
    const float* __restrict__ bias_k, const float* __restrict__ bias_v,
    float* __restrict__ Cext)
{
    const int z = blockIdx.z;
    const int cnt = (MODE == 0) ? NTOK : d_cnt[z];
    const int m0 = blockIdx.y * 128;
    if (m0 >= cnt) return;
    const int n0 = blockIdx.x * 64;
    const int K = 1024, N = 1024;

    const ush *Bh, *Bl;
    if (MODE == 0) { Bh = z ? g_wvh : g_wkh; Bl = z ? g_wvl : g_wkl; }
    else if (MODE == 1) { Bh = g_winh + (size_t)z * K * N; Bl = g_winl + (size_t)z * K * N; }
    else { Bh = g_wouth + (size_t)z * K * N; Bl = g_woutl + (size_t)z * K * N; }

    __shared__ __align__(16) ush As_h[128][40];
    __shared__ __align__(16) ush As_l[128][40];
    __shared__ __align__(16) ush Bs_h[32][88];
    __shared__ __align__(16) ush Bs_l[32][88];

    const int tid = threadIdx.x;
    const int lane = tid & 31;
    const int warp = tid >> 5;
    const int wm = warp >> 1;
    const int wn = warp & 1;

    const int s_row = tid >> 1;
    const int s_half = (tid & 1) * 16;
    const int s_kr = tid >> 3;
    const int s_no = (tid & 7) * 8;

    bool loadv = true;
    const ush *Arh = g_xh, *Arl = g_xl;
    if (MODE == 0) {
        Arh = g_xh + (size_t)(m0 + s_row) * K;
        Arl = g_xl + (size_t)(m0 + s_row) * K;
    } else {
        int r = m0 + s_row;
        if (r < cnt) {
            int enc = d_list[z][r];
            if (MODE == 1) {
                Arh = g_xh + (size_t)(enc >> 1) * K;
                Arl = g_xl + (size_t)(enc >> 1) * K;
            } else {
                Arh = g_ywh + (size_t)enc * K;
                Arl = g_ywl + (size_t)enc * K;
            }
        } else loadv = false;
    }
    const ush* Brh = Bh + (size_t)s_kr * N + n0 + s_no;
    const ush* Brl = Bl + (size_t)s_kr * N + n0 + s_no;

    float acc[2][4][4] = {};

    for (int k0 = 0; k0 < K; k0 += 32) {
        uint4 va0, va1, vb0, vb1;
        if (loadv) {
            va0 = *(const uint4*)(Arh + k0 + s_half);
            va1 = *(const uint4*)(Arh + k0 + s_half + 8);
            vb0 = *(const uint4*)(Arl + k0 + s_half);
            vb1 = *(const uint4*)(Arl + k0 + s_half + 8);
        } else {
            va0 = va1 = vb0 = vb1 = make_uint4(0, 0, 0, 0);
        }
        *(uint4*)&As_h[s_row][s_half]     = va0;
        *(uint4*)&As_h[s_row][s_half + 8] = va1;
        *(uint4*)&As_l[s_row][s_half]     = vb0;
        *(uint4*)&As_l[s_row][s_half + 8] = vb1;
        *(uint4*)&Bs_h[s_kr][s_no] = *(const uint4*)(Brh + (size_t)k0 * N);
        *(uint4*)&Bs_l[s_kr][s_no] = *(const uint4*)(Brl + (size_t)k0 * N);
        __syncthreads();

#pragma unroll
        for (int kc = 0; kc < 2; kc++) {
            u32 Ahf[2][4], Alf[2][4];
            {
                int rowa = wm * 32 + (lane & 7) + ((lane >> 3) & 1) * 8;
                int cola = kc * 16 + (lane >> 4) * 8;
#pragma unroll
                for (int mt = 0; mt < 2; mt++) {
                    ldsm4(Ahf[mt][0], Ahf[mt][1], Ahf[mt][2], Ahf[mt][3],
                          smaddr(&As_h[rowa + mt * 16][cola]));
                    ldsm4(Alf[mt][0], Alf[mt][1], Alf[mt][2], Alf[mt][3],
                          smaddr(&As_l[rowa + mt * 16][cola]));
                }
            }
            u32 Bhf[2][4], Blf[2][4];
            {
                int kb = kc * 16 + (lane & 7) + ((lane >> 3) & 1) * 8;
                int cb0 = wn * 32 + (lane >> 4) * 8;
#pragma unroll
                for (int np = 0; np < 2; np++) {
                    ldsm4t(Bhf[np][0], Bhf[np][1], Bhf[np][2], Bhf[np][3],
                           smaddr(&Bs_h[kb][cb0 + np * 16]));
                    ldsm4t(Blf[np][0], Blf[np][1], Blf[np][2], Blf[np][3],
                           smaddr(&Bs_l[kb][cb0 + np * 16]));
                }
            }
#pragma unroll
            for (int mt = 0; mt < 2; mt++) {
#pragma unroll
                for (int nt = 0; nt < 4; nt++) {
                    int np = nt >> 1;
                    int hi = (nt & 1) * 2;
                    mma_bf16(acc[mt][nt], Ahf[mt], Bhf[np][hi], Bhf[np][hi + 1]);
                    mma_bf16(acc[mt][nt], Ahf[mt], Blf[np][hi], Blf[np][hi + 1]);
                    mma_bf16(acc[mt][nt], Alf[mt], Bhf[np][hi], Bhf[np][hi + 1]);
                }
            }
        }
        __syncthreads();
    }

    const int g = lane >> 2;
    const int tc = (lane & 3) * 2;
    const float* bias = (MODE == 0) ? (z ? bias_v : bias_k) : nullptr;

#pragma unroll
    for (int mt = 0; mt < 2; mt++) {
#pragma unroll
        for (int nt = 0; nt < 4; nt++) {
            int col = n0 + wn * 32 + nt * 8 + tc;
            int rt0 = wm * 32 + mt * 16 + g;
#pragma unroll
            for (int half = 0; half < 2; half++) {
                int r = m0 + rt0 + half * 8;
                float c0 = acc[mt][nt][half * 2 + 0];
                float c1 = acc[mt][nt][half * 2 + 1];
                if (MODE == 0) {
                    c0 += bias[col]; c1 += bias[col + 1];
                    ush h0, l0, h1, l1;
                    split_bf16(c0, h0, l0); split_bf16(c1, h1, l1);
                    size_t idx = (size_t)r * 1024 + col;
                    *(u32*)((z ? g_vh : g_kh) + idx) = (u32)h0 | ((u32)h1 << 16);
                    *(u32*)((z ? g_vl : g_kl) + idx) = (u32)l0 | ((u32)l1 << 16);
                } else if (r < cnt) {
                    int enc = d_list[z][r];
                    if (MODE == 1) {
                        ush h0, l0, h1, l1;
                        split_bf16(c0, h0, l0); split_bf16(c1, h1, l1);
                        size_t idx = (size_t)enc * 1024 + col;
                        *(u32*)(g_qh + idx) = (u32)h0 | ((u32)h1 << 16);
                        *(u32*)(g_ql + idx) = (u32)l0 | ((u32)l1 << 16);
                    } else {
                        float* dst = Cext + (size_t)(enc >> 1) * 1024 + col;
                        atomicAdd(&dst[0], c0);
                        atomicAdd(&dst[1], c1);
                    }
                }
            }
        }
    }
}

// ====== attention logits (tensor): S = Q K^T / sqrt(HS), 64x64 causal tiles ==
// A = q[i][d] (row-major), B = k[j][d] (n-major, k-contig) -> ldsm4 non-trans.
__global__ __launch_bounds__(128) void attn_qk_t() {
    const int jt = blockIdx.x, it = blockIdx.y, bb = blockIdx.z;
    if (jt > it) return;
    const int b = bb >> 4, kk = (bb >> 3) & 1, h = bb & 7;

    __shared__ __align__(16) ush Qh_s[64][40];
    __shared__ __align__(16) ush Ql_s[64][40];
    __shared__ __align__(16) ush Kh_s[64][40];
    __shared__ __align__(16) ush Kl_s[64][40];

    const int tid = threadIdx.x;
    const int lane = tid & 31;
    const int warp = tid >> 5;

    const int s_row = tid >> 1;           // 0..63
    const int s_half = (tid & 1) * 16;    // 0/16

    const size_t qoff = ((size_t)(b * Tc + it * 64 + s_row) * 2 + kk) * AHc + h * HSc;
    const size_t koff = (size_t)(b * Tc + jt * 64 + s_row) * AHc + h * HSc;

    float acc[8][4] = {};

    for (int kt = 0; kt < 4; kt++) {
        const int k0 = kt * 32;
        *(uint4*)&Qh_s[s_row][s_half]     = *(const uint4*)(g_qh + qoff + k0 + s_half);
        *(uint4*)&Qh_s[s_row][s_half + 8] = *(const uint4*)(g_qh + qoff + k0 + s_half + 8);
        *(uint4*)&Ql_s[s_row][s_half]     = *(const uint4*)(g_ql + qoff + k0 + s_half);
        *(uint4*)&Ql_s[s_row][s_half + 8] = *(const uint4*)(g_ql + qoff + k0 + s_half + 8);
        *(uint4*)&Kh_s[s_row][s_half]     = *(const uint4*)(g_kh + koff + k0 + s_half);
        *(uint4*)&Kh_s[s_row][s_half + 8] = *(const uint4*)(g_kh + koff + k0 + s_half + 8);
        *(uint4*)&Kl_s[s_row][s_half]     = *(const uint4*)(g_kl + koff + k0 + s_half);
        *(uint4*)&Kl_s[s_row][s_half + 8] = *(const uint4*)(g_kl + koff + k0 + s_half + 8);
        __syncthreads();

#pragma unroll
        for (int kc = 0; kc < 2; kc++) {
            u32 Ahf[4], Alf[4];
            {
                int rowa = warp * 16 + (lane & 15);
                int cola = kc * 16 + (lane >> 4) * 8;
                ldsm4(Ahf[0], Ahf[1], Ahf[2], Ahf[3], smaddr(&Qh_s[rowa][cola]));
                ldsm4(Alf[0], Alf[1], Alf[2], Alf[3], smaddr(&Ql_s[rowa][cola]));
            }
            // B: non-trans ldsm over [n][k]; per ng (16 n rows):
            //   regs[0]=b0(n0-7), regs[1]=b0(n8-15), regs[2]=b1(n0-7), regs[3]=b1(n8-15)
            u32 BhF[4][4], BlF[4][4];
            {
                int rowb = (lane & 7) + ((lane >> 3) & 1) * 8;
                int colb = kc * 16 + (lane >> 4) * 8;
#pragma unroll
                for (int ng = 0; ng < 4; ng++) {
                    ldsm4(BhF[ng][0], BhF[ng][1], BhF[ng][2], BhF[ng][3],
                          smaddr(&Kh_s[ng * 16 + rowb][colb]));
                    ldsm4(BlF[ng][0], BlF[ng][1], BlF[ng][2], BlF[ng][3],
                          smaddr(&Kl_s[ng * 16 + rowb][colb]));
                }
            }
#pragma unroll
            for (int ng = 0; ng < 4; ng++) {
#pragma unroll
                for (int sub = 0; sub < 2; sub++) {
                    int nt = ng * 2 + sub;
                    u32 bh0 = BhF[ng][sub], bh1 = BhF[ng][sub + 2];
                    u32 bl0 = BlF[ng][sub], bl1 = BlF[ng][sub + 2];
                    mma_bf16(acc[nt], Ahf, bh0, bh1);
                    mma_bf16(acc[nt], Ahf, bl0, bl1);
                    mma_bf16(acc[nt], Alf, bh0, bh1);
                }
            }
        }
        __syncthreads();
    }

    const float scale = 0.08838834764831845f; // 1/sqrt(128)
    const int g = lane >> 2;
    const int tc = (lane & 3) * 2;
    float* obase = d_att + (size_t)bb * (Tc * Tc) + (size_t)(it * 64) * Tc + jt * 64;
#pragma unroll
    for (int nt = 0; nt < 8; nt++) {
        int col = nt * 8 + tc;
#pragma unroll
        for (int half = 0; half < 2; half++) {
            int row = warp * 16 + g + half * 8;
            float* dst = obase + (size_t)row * Tc + col;
            dst[0] = acc[nt][half * 2 + 0] * scale;
            dst[1] = acc[nt][half * 2 + 1] * scale;
        }
    }
}

// ---------------- stick-breaking: f32 logits in, bf16 hi/lo weights out ------
__device__ __forceinline__ float logsig(float a) {
    return (a >= 0.f) ? -__logf(1.f + __expf(-a)) : (a - __logf(1.f + __expf(a)));
}

__global__ __launch_bounds__(256) void stickbreak() {
    const int row = blockIdx.x;
    const int bb = row >> 9;
    const int i = row & (Tc - 1);
    const size_t base = (size_t)bb * (Tc * Tc) + (size_t)i * Tc;
    const float* ap = d_att + base;
    const int tid = threadIdx.x;
    const int j0 = tid * 2, j1 = tid * 2 + 1;
    const bool v0 = (j0 <= i), v1 = (j1 <= i);

    float lz0 = 0.f, lb0 = 0.f, lz1 = 0.f, lb1 = 0.f;
    if (v0) { float a = ap[j0]; lz0 = logsig(a); lb0 = lz0 - a; }
    if (v1) { float a = ap[j1]; lz1 = logsig(a); lb1 = lz1 - a; }

    __shared__ float sc[256];
    float s = lb0 + lb1;
    sc[tid] = s; __syncthreads();
#pragma unroll
    for (int off = 1; off < 256; off <<= 1) {
        float t = (tid >= off) ? sc[tid - off] : 0.f;
        __syncthreads();
        sc[tid] += t;
        __syncthreads();
    }
    const float total = sc[255];
    const float excl = sc[tid] - s;
    float w0 = v0 ? __expf(lz0 + (total - (excl + lb0))) : 0.f;
    float w1 = v1 ? __expf(lz1 + (total - (excl + lb0 + lb1))) : 0.f;

    ush h0, l0, h1, l1;
    split_bf16(w0, h0, l0);
    split_bf16(w1, h1, l1);
    *(u32*)(g_atth + base + j0) = (u32)h0 | ((u32)h1 << 16);
    *(u32*)(g_attl + base + j0) = (u32)l0 | ((u32)l1 << 16);
}

// ====== y = att @ V (tensor), gate-scaled, 64x64 tiles, causal k skip ========
// A = att[i][j] hi/lo, B = v[j][d] ([k][n] k-major) -> ldsm4t like gemm_t.
__global__ __launch_bounds__(128) void attn_av_t() {
    const int nt4 = blockIdx.x, it = blockIdx.y, bb = blockIdx.z;
    const int b = bb >> 4, kk = (bb >> 3) & 1, h = bb & 7;
    const int n0 = nt4 * 64;

    __shared__ __align__(16) ush Ah_s[64][40];
    __shared__ __align__(16) ush Al_s[64][40];
    __shared__ __align__(16) ush Bh_s[32][72];
    __shared__ __align__(16) ush Bl_s[32][72];

    const int tid = threadIdx.x;
    const int lane = tid & 31;
    const int warp = tid >> 5;

    const int sa_row = tid >> 1;          // 0..63
    const int sa_half = (tid & 1) * 16;
    const int sb_row = tid >> 2;          // 0..31
    const int sb_col = (tid & 3) * 16;

    const size_t aoff = (size_t)bb * (Tc * Tc) + (size_t)(it * 64 + sa_row) * Tc;
    const size_t voff0 = (size_t)(b * Tc) * AHc + h * HSc + n0;

    float acc[8][4] = {};
    const int NKT = (it + 1) * 2;   // chunks of 32

    for (int kt = 0; kt < NKT; kt++) {
        const int k0 = kt * 32;
        *(uint4*)&Ah_s[sa_row][sa_half]     = *(const uint4*)(g_atth + aoff + k0 + sa_half);
        *(uint4*)&Ah_s[sa_row][sa_half + 8] = *(const uint4*)(g_atth + aoff + k0 + sa_half + 8);
        *(uint4*)&Al_s[sa_row][sa_half]     = *(const uint4*)(g_attl + aoff + k0 + sa_half);
        *(uint4*)&Al_s[sa_row][sa_half + 8] = *(const uint4*)(g_attl + aoff + k0 + sa_half + 8);
        const size_t voff = voff0 + (size_t)(k0 + sb_row) * AHc + sb_col;
        *(uint4*)&Bh_s[sb_row][sb_col]     = *(const uint4*)(g_vh + voff);
        *(uint4*)&Bh_s[sb_row][sb_col + 8] = *(const uint4*)(g_vh + voff + 8);
        *(uint4*)&Bl_s[sb_row][sb_col]     = *(const uint4*)(g_vl + voff);
        *(uint4*)&Bl_s[sb_row][sb_col + 8] = *(const uint4*)(g_vl + voff + 8);
        __syncthreads();

#pragma unroll
        for (int kc = 0; kc < 2; kc++) {
            u32 Ahf[4], Alf[4];
            {
                int rowa = warp * 16 + (lane & 15);
                int cola = kc * 16 + (lane >> 4) * 8;
                ldsm4(Ahf[0], Ahf[1], Ahf[2], Ahf[3], smaddr(&Ah_s[rowa][cola]));
                ldsm4(Alf[0], Alf[1], Alf[2], Alf[3], smaddr(&Al_s[rowa][cola]));
            }
            u32 BhF[4][4], BlF[4][4];
            {
                int kb = kc * 16 + (lane & 7) + ((lane >> 3) & 1) * 8;
                int cb = (lane >> 4) * 8;
#pragma unroll
                for (int np = 0; np < 4; np++) {
                    ldsm4t(BhF[np][0], BhF[np][1], BhF[np][2], BhF[np][3],
                           smaddr(&Bh_s[kb][np * 16 + cb]));
                    ldsm4t(BlF[np][0], BlF[np][1], BlF[np][2], BlF[np][3],
                           smaddr(&Bl_s[kb][np * 16 + cb]));
                }
            }
#pragma unroll
            for (int nt = 0; nt < 8; nt++) {
                int np = nt >> 1;
                int hi = (nt & 1) * 2;
                mma_bf16(acc[nt], Ahf, BhF[np][hi], BhF[np][hi + 1]);
                mma_bf16(acc[nt], Ahf, BlF[np][hi], BlF[np][hi + 1]);
                mma_bf16(acc[nt], Alf, BhF[np][hi], BhF[np][hi + 1]);
            }
        }
        __syncthreads();
    }

    const int g = lane >> 2;
    const int tc = (lane & 3) * 2;
#pragma unroll
    for (int nt = 0; nt < 8; nt++) {
        int col = h * HSc + n0 + nt * 8 + tc;
#pragma unroll
        for (int half = 0; half < 2; half++) {
            int token = b * Tc + it * 64 + warp * 16 + g + half * 8;
            float gt = d_gates[token * 2 + kk];
            float c0 = acc[nt][half * 2 + 0] * gt;
            float c1 = acc[nt][half * 2 + 1] * gt;
            ush h0, l0, h1, l1;
            split_bf16(c0, h0, l0); split_bf16(c1, h1, l1);
            size_t idx = ((size_t)token * 2 + kk) * AHc + col;
            *(u32*)(g_ywh + idx) = (u32)h0 | ((u32)h1 << 16);
            *(u32*)(g_ywl + idx) = (u32)l0 | ((u32)l1 << 16);
        }
    }
}

// ---------------- launch ----------------
extern "C" void kernel_launch(void* const* d_in, const int* in_sizes, int n_in,
                              void* d_out, int out_size) {
    const float* x     = (const float*)d_in[0];
    const float* Wg    = (const float*)d_in[1];
    const float* W_in  = (const float*)d_in[2];
    const float* W_out = (const float*)d_in[3];
    const float* Wk    = (const float*)d_in[4];
    const float* bk    = (const float*)d_in[5];
    const float* Wv    = (const float*)d_in[6];
    const float* bv    = (const float*)d_in[7];
    float* out = (float*)d_out;

    zero_kernel<<<(NTOK * Cc + 255) / 256, 256>>>(out);
    gate_kernel<<<(NTOK * 32 + 127) / 128, 128>>>(x, Wg);

    // bf16 hi/lo splits (4 float4 per thread)
    cvt_split<0><<<256, 256>>>(x, NTOK * Cc);
    cvt_split<1><<<256, 256>>>(Wk, Cc * AHc);
    cvt_split<2><<<256, 256>>>(Wv, Cc * AHc);
    cvt_split<3><<<2048, 256>>>(W_in, Ec * Cc * AHc);
    cvt_split<4><<<2048, 256>>>(W_out, Ec * AHc * Cc);

    // K and V projections (tensor, z selects) -> bf16 hi/lo
    gemm_t<0><<<dim3(16, 8, 2), 256>>>(bk, bv, nullptr);

    // grouped q projection (tensor) -> bf16 hi/lo
    gemm_t<1><<<dim3(16, 16, Ec), 256>>>(nullptr, nullptr, nullptr);

    // attention logits (tensor, causal 64x64 tiles) -> f32 d_att
    attn_qk_t<<<dim3(8, 8, NBATCH), 128>>>();

    // stick-breaking -> bf16 hi/lo weights
    stickbreak<<<NBATCH * Tc, 256>>>();

    // y = att @ V (tensor), gate scaled -> bf16 hi/lo yw
    attn_av_t<<<dim3(2, 8, NBATCH), 128>>>();

    // grouped output projection (tensor), scatter-add f32 into out
    gemm_t<2><<<dim3(16, 16, Ec), 256>>>(nullptr, nullptr, out);

    // aux loss scalar
    aux_kernel<<<1, 256>>>(out, out_size);
}